// round 15
// baseline (speedup 1.0000x reference)
#include <cuda_runtime.h>
#include <cuda_fp16.h>
#include <cuda_fp8.h>
#include <cstdint>

// ---------------------------------------------------------------------------
// Qwen2 FP8 MLP, fp16 tcgen05 cg2 persistent + fp8 weight delivery.
//   R15: exact K-balanced GEMM2. 37888 (tile,kt) units split 512/pair
//   (74*512 == 128*296). Boundary tiles (split between 2 pairs) combine
//   scaled partials via red.global.add.f32 into pre-zeroed out; full tiles
//   use plain stores. Removes the ceil(128/74)=2 wave imbalance (~45us).
//   GEMM1 + dynamic converter unchanged from R14.
// ---------------------------------------------------------------------------

#if defined(__CUDA_ARCH_FEAT_SM103_ALL) || defined(__CUDA_ARCH_FEAT_SM100_ALL) || defined(__CUDA_ARCH_SPECIFIC__)
#define USE_TCGEN05 1
#else
#define USE_TCGEN05 0
#endif

namespace {
constexpr int HIDDEN = 3584;
constexpr int INTER  = 18944;
constexpr int TOKENS = 4096;

constexpr int KC      = 64;
constexpr int NSTG    = 4;
constexpr int THREADS = 448;      // w0 MMA, w1 prod, w2-3 dequant, w4-11 epi, w12-13 conv
constexpr int NPAIRS  = 74;

constexpr int A_BYTES = 32768;
constexpr int ATILE   = 65536;

constexpr int KT1 = HIDDEN / KC;              // 56
constexpr int KT2 = INTER  / KC;              // 296

constexpr int NB1      = INTER / 128;         // 148
constexpr int BB1      = 16384;
constexpr int BR1      = 8192;
constexpr int BTILE1R  = 16384;
constexpr int NT1      = (TOKENS / 512) * NB1;

constexpr int N2       = 224;
constexpr int NB2      = HIDDEN / N2;         // 16
constexpr int BB2      = 14336;
constexpr int BR2      = 7168;
constexpr int BTILE2R  = 14336;

constexpr int UNITS_PP = 512;                 // 74*512 == 128*296 exactly

constexpr int PRECONV   = 18;
constexpr int PRE_CHUNKS = PRECONV * KT1 * 1024;
constexpr int X_CHUNKS   = (TOKENS / 512) * KT1 * 4096;
constexpr int OUT_CHUNKS = (TOKENS * HIDDEN) / 4;     // float4 zero chunks
constexpr int WGU_UNITS  = (NB1 - PRECONV) * KT1;
constexpr int WD_UNITS   = NB2 * KT2;
constexpr int TOTAL_UNITS = WGU_UNITS + WD_UNITS;
}

__device__ __half   g_x16[(size_t)(TOKENS / 512) * KT1 * (ATILE / 2)];
__device__ uint8_t  g_wgu8[(size_t)NB1 * KT1 * BTILE1R];
__device__ uint8_t  g_wd8 [(size_t)NB2 * KT2 * BTILE2R];
__device__ __half   g_h16[(size_t)(TOKENS / 512) * KT2 * (ATILE / 2)];

__device__ uint32_t g_uctr;
__device__ uint32_t g_wdone[NB1];

__host__ __device__ __forceinline__ uint32_t swz(uint32_t off) {
    return off ^ ((off >> 3) & 0x70);
}

__device__ __forceinline__ uint32_t pack_e4m3_4(float f0, float f1, float f2, float f3) {
    uint32_t w;
    asm("{\n\t.reg .b16 p0, p1;\n\t"
        "cvt.rn.satfinite.e4m3x2.f32 p0, %2, %1;\n\t"
        "cvt.rn.satfinite.e4m3x2.f32 p1, %4, %3;\n\t"
        "mov.b32 %0, {p0, p1};\n\t}"
        : "=r"(w) : "f"(f0), "f"(f1), "f"(f2), "f"(f3));
    return w;
}
__device__ __forceinline__ void fp8x4_to_h2x2(uint32_t w, uint32_t& o0, uint32_t& o1) {
    asm("{\n\t.reg .b16 lo, hi;\n\t"
        "mov.b32 {lo, hi}, %2;\n\t"
        "cvt.rn.f16x2.e4m3x2 %0, lo;\n\t"
        "cvt.rn.f16x2.e4m3x2 %1, hi;\n\t}"
        : "=r"(o0), "=r"(o1) : "r"(w));
}
__device__ __forceinline__ void stg_cg_v4(void* p, uint4 v) {
    asm volatile("st.global.cg.v4.u32 [%0], {%1,%2,%3,%4};"
                 :: "l"(p), "r"(v.x), "r"(v.y), "r"(v.z), "r"(v.w) : "memory");
}
__device__ __forceinline__ void red_add_f32(float* p, float v) {
    asm volatile("red.global.add.f32 [%0], %1;" :: "l"(p), "f"(v) : "memory");
}

__device__ __forceinline__ void conv_wgu8_chunk(const float* __restrict__ src,
                                                int tile, int c) {
    const int tr = c >> 2;
    const int ch = c & 3;
    const int kt = tile % KT1;
    const int nb = tile / KT1;
    const int grow = (tr < 128) ? (nb * 128 + tr) : (INTER + nb * 128 + (tr - 128));
    const float* s = src + (size_t)grow * HIDDEN + kt * KC + ch * 16;
    uint32_t w[4];
    #pragma unroll
    for (int q = 0; q < 4; q++) {
        float4 f = reinterpret_cast<const float4*>(s)[q];
        w[q] = pack_e4m3_4(f.x, f.y, f.z, f.w);
    }
    uint8_t* dst = g_wgu8 + (size_t)tile * BTILE1R
                 + (tr >> 7) * BR1 + (tr & 127) * 64 + ch * 16;
    stg_cg_v4(dst, make_uint4(w[0], w[1], w[2], w[3]));
}

__device__ __forceinline__ void conv_wd8_chunk(const float* __restrict__ src, int gid) {
    const int tile = gid / 896;
    const int c    = gid % 896;
    const int tr   = c >> 2;
    const int ch   = c & 3;
    const int kt   = tile % KT2;
    const int bb   = tile / KT2;
    const int grow = bb * N2 + tr;
    const float* s = src + (size_t)grow * INTER + kt * KC + ch * 16;
    uint32_t w[4];
    #pragma unroll
    for (int q = 0; q < 4; q++) {
        float4 f = reinterpret_cast<const float4*>(s)[q];
        w[q] = pack_e4m3_4(f.x, f.y, f.z, f.w);
    }
    const int half = tr / 112;
    const int wr   = tr - half * 112;
    uint8_t* dst = g_wd8 + (size_t)tile * BTILE2R + half * BR2 + wr * 64 + ch * 16;
    *reinterpret_cast<uint4*>(dst) = make_uint4(w[0], w[1], w[2], w[3]);
}

// ---------------------------------------------------------------------------
// prep: zero converter state + out, w_gu stripes [0, PRECONV), x
// ---------------------------------------------------------------------------
__global__ void __launch_bounds__(256) conv_prep(const float* __restrict__ w_gu,
                                                 const float* __restrict__ x,
                                                 float* __restrict__ out) {
    int gid = blockIdx.x * 256 + threadIdx.x;
    if (gid == 0) g_uctr = 0;
    if (gid >= 1 && gid <= NB1) g_wdone[gid - 1] = 0;

    if (gid < PRE_CHUNKS) {
        conv_wgu8_chunk(w_gu, gid >> 10, gid & 1023);
        return;
    }
    gid -= PRE_CHUNKS;
    if (gid < X_CHUNKS) {
        const int tile = gid >> 12;
        const int c    = gid & 4095;
        const int sr   = c >> 3;
        const int ch   = c & 7;
        const int kt   = tile % KT1;
        const int mb   = tile / KT1;
        const int rank = sr >> 8;
        const int wr   = sr & 255;
        const int m    = mb * 512 + (wr >> 7) * 256 + rank * 128 + (wr & 127);
        const float* s = x + (size_t)m * HIDDEN + kt * KC + ch * 8;
        float4 a = *reinterpret_cast<const float4*>(s);
        float4 b = *reinterpret_cast<const float4*>(s + 4);
        __half2 p0 = __floats2half2_rn(a.x, a.y);
        __half2 p1 = __floats2half2_rn(a.z, a.w);
        __half2 p2 = __floats2half2_rn(b.x, b.y);
        __half2 p3 = __floats2half2_rn(b.z, b.w);
        uint4 v = make_uint4(*reinterpret_cast<uint32_t*>(&p0),
                             *reinterpret_cast<uint32_t*>(&p1),
                             *reinterpret_cast<uint32_t*>(&p2),
                             *reinterpret_cast<uint32_t*>(&p3));
        char* dst = reinterpret_cast<char*>(g_x16) + (size_t)tile * ATILE
                  + rank * 32768 + swz((uint32_t)(wr * 128 + ch * 16));
        *reinterpret_cast<uint4*>(dst) = v;
        return;
    }
    gid -= X_CHUNKS;
    if (gid < OUT_CHUNKS) {
        reinterpret_cast<float4*>(out)[gid] = make_float4(0.f, 0.f, 0.f, 0.f);
    }
}

// ---------------------------------------------------------------------------
// device helpers
// ---------------------------------------------------------------------------
#if USE_TCGEN05
__device__ __forceinline__ bool elect_one() {
    uint32_t p;
    asm volatile("{\n\t.reg .pred p;\n\telect.sync _|p, 0xFFFFFFFF;\n\t"
                 "selp.b32 %0, 1, 0, p;\n\t}" : "=r"(p));
    return p != 0;
}
__device__ __forceinline__ uint32_t ctarank() {
    uint32_t r;
    asm("mov.u32 %0, %%cluster_ctarank;" : "=r"(r));
    return r;
}
__device__ __forceinline__ void mbar_init(uint32_t addr, uint32_t count) {
    asm volatile("mbarrier.init.shared.b64 [%0], %1;" :: "r"(addr), "r"(count) : "memory");
}
__device__ __forceinline__ void mbar_wait(uint32_t addr, uint32_t parity) {
    asm volatile(
        "{\n\t.reg .pred P;\n\t"
        "WL_%=:\n\t"
        "mbarrier.try_wait.parity.acquire.cta.shared::cta.b64 P, [%0], %1, 0x989680;\n\t"
        "@P bra.uni WD_%=;\n\t"
        "bra.uni WL_%=;\n\t"
        "WD_%=:\n\t}"
        :: "r"(addr), "r"(parity) : "memory");
}
__device__ __forceinline__ void mbar_expect_tx(uint32_t addr, uint32_t bytes) {
    asm volatile("mbarrier.arrive.expect_tx.shared.b64 _, [%0], %1;"
                 :: "r"(addr), "r"(bytes) : "memory");
}
__device__ __forceinline__ void mbar_arrive(uint32_t addr) {
    asm volatile("mbarrier.arrive.shared.b64 _, [%0];" :: "r"(addr) : "memory");
}
__device__ __forceinline__ void mbar_arrive_remote(uint32_t local_addr, uint32_t target_rank) {
    asm volatile(
        "{\n\t.reg .b32 ra;\n\t"
        "mapa.shared::cluster.u32 ra, %0, %1;\n\t"
        "mbarrier.arrive.shared::cluster.b64 _, [ra];\n\t}"
        :: "r"(local_addr), "r"(target_rank) : "memory");
}
__device__ __forceinline__ void bulk_g2s(uint32_t dst, const void* src, uint32_t bytes,
                                         uint32_t mbar) {
    asm volatile(
        "cp.async.bulk.shared::cluster.global.mbarrier::complete_tx::bytes "
        "[%0], [%1], %2, [%3];"
        :: "r"(dst), "l"(src), "r"(bytes), "r"(mbar) : "memory");
}
__device__ __forceinline__ void tc_alloc_cg2(uint32_t dst_smem, uint32_t ncols) {
    asm volatile("tcgen05.alloc.cta_group::2.sync.aligned.shared::cta.b32 [%0], %1;"
                 :: "r"(dst_smem), "r"(ncols) : "memory");
}
__device__ __forceinline__ void tc_relinquish_cg2() {
    asm volatile("tcgen05.relinquish_alloc_permit.cta_group::2.sync.aligned;");
}
__device__ __forceinline__ void tc_dealloc_cg2(uint32_t tmem, uint32_t ncols) {
    asm volatile("tcgen05.dealloc.cta_group::2.sync.aligned.b32 %0, %1;"
                 :: "r"(tmem), "r"(ncols));
}
__device__ __forceinline__ void tc_commit_mc_cg2(uint32_t mbar, uint16_t mask) {
    asm volatile(
        "tcgen05.commit.cta_group::2.mbarrier::arrive::one.shared::cluster.multicast::cluster.b64 "
        "[%0], %1;"
        :: "r"(mbar), "h"(mask) : "memory");
}
__device__ __forceinline__ void tc_wait_ld() {
    asm volatile("tcgen05.wait::ld.sync.aligned;" ::: "memory");
}
__device__ __forceinline__ uint64_t sdesc(uint32_t addr) {
    return ((uint64_t)((addr >> 4) & 0x3FFF))
         | (1ULL  << 16) | (64ULL << 32) | (1ULL << 46) | (2ULL << 61);
}
__device__ __forceinline__ void mma_f16_ss_cg2(uint32_t d_tmem, uint64_t ad, uint64_t bd,
                                               uint32_t idesc, uint32_t enable_d) {
    asm volatile(
        "{\n\t.reg .pred p;\n\t"
        "setp.ne.u32 p, %4, 0;\n\t"
        "tcgen05.mma.cta_group::2.kind::f16 [%0], %1, %2, %3, "
        "{%5,%5,%5,%5,%5,%5,%5,%5}, p;\n\t}"
        :: "r"(d_tmem), "l"(ad), "l"(bd), "r"(idesc), "r"(enable_d), "r"(0u)
        : "memory");
}
__device__ __forceinline__ void ldtm32(uint32_t* r, uint32_t ta) {
    asm volatile(
        "tcgen05.ld.sync.aligned.32x32b.x32.b32 "
        "{%0,%1,%2,%3,%4,%5,%6,%7,%8,%9,%10,%11,%12,%13,%14,%15,"
        "%16,%17,%18,%19,%20,%21,%22,%23,%24,%25,%26,%27,%28,%29,%30,%31}, [%32];"
        : "=r"(r[0]),  "=r"(r[1]),  "=r"(r[2]),  "=r"(r[3]),
          "=r"(r[4]),  "=r"(r[5]),  "=r"(r[6]),  "=r"(r[7]),
          "=r"(r[8]),  "=r"(r[9]),  "=r"(r[10]), "=r"(r[11]),
          "=r"(r[12]), "=r"(r[13]), "=r"(r[14]), "=r"(r[15]),
          "=r"(r[16]), "=r"(r[17]), "=r"(r[18]), "=r"(r[19]),
          "=r"(r[20]), "=r"(r[21]), "=r"(r[22]), "=r"(r[23]),
          "=r"(r[24]), "=r"(r[25]), "=r"(r[26]), "=r"(r[27]),
          "=r"(r[28]), "=r"(r[29]), "=r"(r[30]), "=r"(r[31])
        : "r"(ta));
}
#endif

// fallback read helpers
__device__ __forceinline__ float rd_a(const __half* buf, int KT, int m, int k) {
    const int mb = m >> 9, mm = m & 511;
    const int rank = (mm >> 7) & 1;
    const int wr = ((mm >> 8) << 7) | (mm & 127);
    const char* p = reinterpret_cast<const char*>(buf)
                  + ((size_t)mb * KT + (k >> 6)) * ATILE + rank * 32768
                  + swz((uint32_t)(wr * 128 + ((k & 63) >> 3) * 16)) + (k & 7) * 2;
    return __half2float(*reinterpret_cast<const __half*>(p));
}
__device__ __forceinline__ float rd_b8(const uint8_t* buf, int KT, int tile_b, int tr, int k,
                                       int tile_bytes, int half_rows) {
    const int half = tr / half_rows;
    const int wr   = tr - half * half_rows;
    const uint8_t* p = buf + ((size_t)tile_b * KT + (k >> 6)) * tile_bytes
                     + half * (tile_bytes / 2) + wr * 64 + (k & 63);
    __nv_fp8_e4m3 v;
    *reinterpret_cast<uint8_t*>(&v) = *p;
    return float(v);
}

// ---------------------------------------------------------------------------
// Persistent GEMM. grid (148,1,1), cluster (2,1,1), 448 threads.
// MODE 0: 16 tiles/pair mb-major + chip-wide dynamic converter (warps 12-13).
// MODE 1: flat 512 kt-units/pair over 2-3 tile segments; boundary segments
//         combined via red.global.add into pre-zeroed out.
// ---------------------------------------------------------------------------
template <int MODE>
__global__ void __launch_bounds__(THREADS, 1) __cluster_dims__(2, 1, 1)
mlp_gemm(const float* __restrict__ S, float* __restrict__ Out,
         const float* __restrict__ Wgu32, const float* __restrict__ Wd32)
{
    constexpr int KT      = (MODE == 0) ? KT1 : KT2;
    constexpr int NMMA    = (MODE == 0) ? 256 : N2;
    constexpr int BBYTES  = (MODE == 0) ? BB1 : BB2;
    constexpr int BRAW    = (MODE == 0) ? BR1 : BR2;
    constexpr int BTILER  = (MODE == 0) ? BTILE1R : BTILE2R;
    constexpr int STG_B   = A_BYTES + BBYTES + BRAW;
    constexpr int DQU     = (MODE == 0) ? 8 : 7;
    const int pair = blockIdx.x >> 1;
    const int ntp  = NT1 / NPAIRS;   // MODE 0 tiles per pair (16)

    extern __shared__ char smem[];
    const int t    = threadIdx.x;
    const int wid  = t >> 5;
    const int lane = t & 31;

#if USE_TCGEN05
    constexpr uint32_t IDESC = (1u << 4) | ((uint32_t)(NMMA / 8) << 17) | (16u << 24);

    const uint32_t sbase     = (uint32_t)__cvta_generic_to_shared(smem);
    const uint32_t tptr_addr = sbase;
    const uint32_t bar_full  = sbase + 8;
    const uint32_t bar_empty = bar_full + NSTG * 8;
    const uint32_t bar_deq   = bar_empty + NSTG * 8;
    const uint32_t bar_done  = bar_deq + NSTG * 8;
    const uint32_t bar_elo   = bar_done + 8;
    const uint32_t bar_ehi   = bar_done + 16;
    const uint32_t data_u    = (sbase + 256 + 1023) & ~1023u;
    const uint32_t rank      = ctarank();

    // MODE 1: segment table (2-3 segments of [k0,k1) within tiles T)
    int segT[3], segK0[3], segK1[3], nseg = 0;
    if (MODE == 1) {
        const int ustart = UNITS_PP * pair;
        const int Tf = ustart / KT2, Tl = (ustart + UNITS_PP - 1) / KT2;
        for (int T = Tf; T <= Tl; T++) {
            int k0 = ustart - T * KT2; if (k0 < 0) k0 = 0;
            int k1 = ustart + UNITS_PP - T * KT2; if (k1 > KT2) k1 = KT2;
            segT[nseg] = T; segK0[nseg] = k0; segK1[nseg] = k1; nseg++;
        }
    }

    auto tile_mb_nb = [&](int tl, int& mb, int& nb) {   // MODE 0 map
        const int idx = tl * NPAIRS + pair;
        mb = idx & 7; nb = idx >> 3;
    };

    if (wid == 0) { tc_alloc_cg2(tptr_addr, 512); tc_relinquish_cg2(); }
    if (t == 0) {
        for (int s = 0; s < NSTG; s++) {
            mbar_init(bar_full  + s * 8, 1);
            mbar_init(bar_empty + s * 8, 1);
            mbar_init(bar_deq   + s * 8, 4);
        }
        mbar_init(bar_done, 1);
        mbar_init(bar_elo, 8);
        mbar_init(bar_ehi, 8);
    }
    __syncthreads();
    asm volatile("barrier.cluster.arrive.aligned;" ::: "memory");
    asm volatile("barrier.cluster.wait.aligned;"   ::: "memory");

    uint32_t tmem;
    asm volatile("ld.shared.b32 %0, [%1];" : "=r"(tmem) : "r"(tptr_addr));

    const char*    Abuf = reinterpret_cast<const char*>((MODE == 0) ? g_x16 : g_h16);
    const uint8_t* Bbuf = (MODE == 0) ? g_wgu8 : g_wd8;

    if (t == 32) {
        // ---------------- TMA producer ----------------
        uint32_t g = 0;
        if (MODE == 0) {
            for (int tl = 0; tl < ntp; tl++) {
                int mb, nb; tile_mb_nb(tl, mb, nb);
                if (nb >= PRECONV) {
                    uint32_t v;
                    const uint32_t* fp = &g_wdone[nb];
                    do {
                        asm volatile("ld.acquire.gpu.global.u32 %0, [%1];"
                                     : "=r"(v) : "l"(fp) : "memory");
                    } while (v < (uint32_t)KT1);
                }
                const char*    a_base = Abuf + (size_t)mb * KT * ATILE + rank * 32768;
                const uint8_t* b_base = Bbuf + (size_t)nb * KT * BTILER + rank * BRAW;
                for (int kt = 0; kt < KT; kt++, g++) {
                    const uint32_t s = g & (NSTG - 1);
                    if (g >= NSTG) mbar_wait(bar_empty + s * 8, ((g >> 2) - 1) & 1);
                    const uint32_t As = data_u + s * STG_B;
                    mbar_expect_tx(bar_full + s * 8, A_BYTES + BRAW);
                    bulk_g2s(As, a_base + (size_t)kt * ATILE, A_BYTES, bar_full + s * 8);
                    bulk_g2s(As + A_BYTES + BBYTES, b_base + (size_t)kt * BTILER, BRAW,
                             bar_full + s * 8);
                }
            }
        } else {
            for (int sg = 0; sg < nseg; sg++) {
                const int mb = segT[sg] & 7, nb = segT[sg] >> 3;
                const char*    a_base = Abuf + (size_t)mb * KT * ATILE + rank * 32768;
                const uint8_t* b_base = Bbuf + (size_t)nb * KT * BTILER + rank * BRAW;
                for (int kt = segK0[sg]; kt < segK1[sg]; kt++, g++) {
                    const uint32_t s = g & (NSTG - 1);
                    if (g >= NSTG) mbar_wait(bar_empty + s * 8, ((g >> 2) - 1) & 1);
                    const uint32_t As = data_u + s * STG_B;
                    mbar_expect_tx(bar_full + s * 8, A_BYTES + BRAW);
                    bulk_g2s(As, a_base + (size_t)kt * ATILE, A_BYTES, bar_full + s * 8);
                    bulk_g2s(As + A_BYTES + BBYTES, b_base + (size_t)kt * BTILER, BRAW,
                             bar_full + s * 8);
                }
            }
        }
    } else if (wid == 2 || wid == 3) {
        // ---------------- dequant warps: fp8 raw -> fp16 SW128 in SMEM --------
        const int wt = t - 64;
        const uint32_t total = (MODE == 0) ? (uint32_t)ntp * KT : (uint32_t)UNITS_PP;
        for (uint32_t g = 0; g < total; g++) {
            const uint32_t s = g & (NSTG - 1);
            mbar_wait(bar_full + s * 8, (g >> 2) & 1);
            const uint32_t As  = data_u + s * STG_B;
            const uint32_t dst = As + A_BYTES;
            const uint32_t raw = dst + BBYTES;
            #pragma unroll
            for (int j = 0; j < DQU; j++) {
                const int u   = wt + 64 * j;
                const int row = u >> 2;
                const int ch  = u & 3;
                uint4 r;
                asm volatile("ld.shared.v4.u32 {%0,%1,%2,%3}, [%4];"
                             : "=r"(r.x), "=r"(r.y), "=r"(r.z), "=r"(r.w)
                             : "r"(raw + row * 64 + ch * 16));
                uint32_t o0, o1, o2, o3, o4, o5, o6, o7;
                fp8x4_to_h2x2(r.x, o0, o1);
                fp8x4_to_h2x2(r.y, o2, o3);
                fp8x4_to_h2x2(r.z, o4, o5);
                fp8x4_to_h2x2(r.w, o6, o7);
                const uint32_t ob = (uint32_t)(row * 128 + ch * 32);
                asm volatile("st.shared.v4.b32 [%0], {%1,%2,%3,%4};"
                             :: "r"(dst + swz(ob)), "r"(o0), "r"(o1), "r"(o2), "r"(o3)
                             : "memory");
                asm volatile("st.shared.v4.b32 [%0], {%1,%2,%3,%4};"
                             :: "r"(dst + swz(ob + 16)), "r"(o4), "r"(o5), "r"(o6), "r"(o7)
                             : "memory");
            }
            asm volatile("fence.proxy.async.shared::cta;" ::: "memory");
            if (elect_one()) {
                if (rank == 0) mbar_arrive(bar_deq + s * 8);
                else           mbar_arrive_remote(bar_deq + s * 8, 0);
            }
        }
    } else if (wid == 0 && rank == 0) {
        // ---------------- MMA issuer (leader) ----------------
        if (elect_one()) {
            uint32_t g = 0;
            int sidx = 0;
            const int nloops = (MODE == 0) ? ntp : nseg;
            for (int li = 0; li < nloops; li++) {
                const int k0 = (MODE == 0) ? 0  : segK0[li];
                const int k1 = (MODE == 0) ? KT : segK1[li];
                for (int kt = k0; kt < k1; kt++, g++) {
                    const uint32_t s = g & (NSTG - 1);
                    mbar_wait(bar_deq + s * 8, (g >> 2) & 1);
                    const uint32_t As = data_u + s * STG_B;
                    const uint64_t ad0 = sdesc(As);
                    const uint64_t ad1 = sdesc(As + 16384);
                    const uint64_t bd  = sdesc(As + A_BYTES);
                    if (kt == k0) {
                        if (sidx > 0) mbar_wait(bar_elo, (sidx - 1) & 1);
                        #pragma unroll
                        for (int kk = 0; kk < 4; kk++)
                            mma_f16_ss_cg2(tmem, ad0 + 2 * kk, bd + 2 * kk, IDESC, kk > 0);
                        if (sidx > 0) mbar_wait(bar_ehi, (sidx - 1) & 1);
                        #pragma unroll
                        for (int kk = 0; kk < 4; kk++)
                            mma_f16_ss_cg2(tmem + NMMA, ad1 + 2 * kk, bd + 2 * kk, IDESC, kk > 0);
                    } else {
                        #pragma unroll
                        for (int kk = 0; kk < 4; kk++) {
                            mma_f16_ss_cg2(tmem,        ad0 + 2 * kk, bd + 2 * kk, IDESC, 1);
                            mma_f16_ss_cg2(tmem + NMMA, ad1 + 2 * kk, bd + 2 * kk, IDESC, 1);
                        }
                    }
                    tc_commit_mc_cg2(bar_empty + s * 8, (uint16_t)0x3);
                }
                tc_commit_mc_cg2(bar_done, (uint16_t)0x3);
                sidx++;
            }
        }
    } else if (wid >= 4 && wid < 12) {
        // ---------------- epilogue warps ----------------
        const int mh = (wid >> 2) - 1;
        const int sp = wid & 3;
        const uint32_t tbase = tmem + mh * NMMA;
        const uint32_t ebar  = (mh == 0) ? bar_elo : bar_ehi;
        const int nloops = (MODE == 0) ? ntp : nseg;
        for (int li = 0; li < nloops; li++) {
            int mb, nb;
            bool full = true;
            if (MODE == 0) tile_mb_nb(li, mb, nb);
            else {
                mb = segT[li] & 7; nb = segT[li] >> 3;
                full = (segK0[li] == 0) && (segK1[li] == KT2);
            }
            mbar_wait(bar_done, li & 1);
            asm volatile("tcgen05.fence::after_thread_sync;" ::: "memory");
            const int m = mb * 512 + mh * 256 + (int)rank * 128 + sp * 32 + lane;

            if (MODE == 0) {
                const int n0 = nb * 128;
                const int mm = m & 511;
                const int rank2 = (mm >> 7) & 1;
                const int wr2 = ((mm >> 8) << 7) | (mm & 127);
                char* hb = reinterpret_cast<char*>(g_h16)
                         + (size_t)(m >> 9) * KT2 * ATILE + rank2 * 32768;
                #pragma unroll
                for (int c = 0; c < 4; c++) {
                    const int cb = c * 32;
                    uint32_t gr[32], ur[32];
                    ldtm32(gr, tbase + cb);
                    ldtm32(ur, tbase + 128 + cb);
                    tc_wait_ld();
                    if (c == 3) {
                        if (elect_one()) mbar_arrive_remote(ebar, 0);
                    }
                    uint32_t oh[16];
                    #pragma unroll
                    for (int p = 0; p < 16; p++) {
                        const int i = 2 * p;
                        const int n = n0 + cb + i;
                        float g0 = __uint_as_float(gr[i])     * __ldg(S + n);
                        float g1 = __uint_as_float(gr[i + 1]) * __ldg(S + n + 1);
                        float u0 = __uint_as_float(ur[i])     * __ldg(S + INTER + n);
                        float u1 = __uint_as_float(ur[i + 1]) * __ldg(S + INTER + n + 1);
                        float h0 = __fdividef(g0, 1.0f + __expf(-g0)) * u0;
                        float h1 = __fdividef(g1, 1.0f + __expf(-g1)) * u1;
                        __half2 ph = __floats2half2_rn(h0, h1);
                        oh[p] = *reinterpret_cast<uint32_t*>(&ph);
                    }
                    #pragma unroll
                    for (int q = 0; q < 4; q++) {
                        const int col = n0 + cb + q * 8;
                        char* tb = hb + (size_t)(col >> 6) * ATILE;
                        const uint32_t off = swz((uint32_t)(wr2 * 128 + ((col & 63) >> 3) * 16));
                        *reinterpret_cast<uint4*>(tb + off) =
                            make_uint4(oh[4 * q], oh[4 * q + 1], oh[4 * q + 2], oh[4 * q + 3]);
                    }
                }
            } else {
                const int n0 = nb * N2;
                float* op = Out + (size_t)m * HIDDEN + n0;
                #pragma unroll
                for (int c = 0; c < 7; c++) {
                    const int cb = c * 32;
                    uint32_t dr[32];
                    ldtm32(dr, tbase + cb);
                    tc_wait_ld();
                    if (c == 6) {
                        if (elect_one()) mbar_arrive_remote(ebar, 0);
                    }
                    #pragma unroll
                    for (int q = 0; q < 8; q++) {
                        float r[4];
                        #pragma unroll
                        for (int j = 0; j < 4; j++) {
                            const int i = q * 4 + j;
                            r[j] = __uint_as_float(dr[i]) * __ldg(S + n0 + cb + i);
                        }
                        if (full) {
                            reinterpret_cast<float4*>(op + cb)[q] =
                                make_float4(r[0], r[1], r[2], r[3]);
                        } else {
                            float* bp = op + cb + q * 4;
                            red_add_f32(bp + 0, r[0]);
                            red_add_f32(bp + 1, r[1]);
                            red_add_f32(bp + 2, r[2]);
                            red_add_f32(bp + 3, r[3]);
                        }
                    }
                }
            }
        }
    } else if (MODE == 0 && wid >= 12) {
        // ---------------- chip-wide dynamic converter ----------------
        for (;;) {
            uint32_t u;
            if (lane == 0) u = atomicAdd(&g_uctr, 1u);
            u = __shfl_sync(0xFFFFFFFFu, u, 0);
            if (u >= (uint32_t)TOTAL_UNITS) break;
            if (u < (uint32_t)WGU_UNITS) {
                const int tile = PRECONV * KT1 + (int)u;
                const int nb   = tile / KT1;
                #pragma unroll 4
                for (int j = 0; j < 32; j++)
                    conv_wgu8_chunk(Wgu32, tile, lane + 32 * j);
                __syncwarp();
                if (lane == 0) {
                    uint32_t* dp = &g_wdone[nb];
                    asm volatile("red.release.gpu.global.add.u32 [%0], %1;"
                                 :: "l"(dp), "r"(1u) : "memory");
                }
            } else {
                const int t2 = (int)u - WGU_UNITS;
                #pragma unroll 4
                for (int j = 0; j < 28; j++)
                    conv_wd8_chunk(Wd32, t2 * 896 + lane + 32 * j);
            }
        }
    }

    __syncthreads();
    if (wid == 0) tc_dealloc_cg2(tmem, 512);
    asm volatile("barrier.cluster.arrive.aligned;" ::: "memory");
    asm volatile("barrier.cluster.wait.aligned;"   ::: "memory");

#else
    // non-103a compile pass only (never selected at runtime on GB300)
    (void)smem; (void)lane;
    const int rankf = blockIdx.x & 1;
    constexpr int KTOT = (MODE == 0) ? HIDDEN : INTER;
    constexpr int NCOL = (MODE == 0) ? 128 : N2;
    const int ntpf = (MODE == 0) ? ntp
                                 : ((pair < (TOKENS / 512) * NB2 - NPAIRS) ? 2 : 1);
    if (MODE == 0) {
        for (int tl = 0; tl < ntpf; tl++) {
            const int idx = tl * NPAIRS + pair;
            const int nb = idx >> 3;
            for (int u = t; u < KT1 * 1024; u += THREADS)
                conv_wgu8_chunk(Wgu32, nb * KT1 + (u >> 10), u & 1023);
        }
        for (int g = (int)blockIdx.x * THREADS + t; g < NB2 * KT2 * 896;
             g += 148 * THREADS)
            conv_wd8_chunk(Wd32, g);
        __syncthreads();
    }
    for (int tl = 0; tl < ntpf; tl++) {
        const int idx = tl * NPAIRS + pair;
        const int mb = idx & 7, nb = idx >> 3;
        const int n0 = nb * NCOL;
        for (int o = t; o < 256 * NCOL; o += THREADS) {
            const int rr = o / NCOL, cc = o % NCOL;
            const int m = mb * 512 + (rr >> 7) * 256 + rankf * 128 + (rr & 127);
            if (MODE == 0) {
                float accg = 0.f, accu = 0.f;
                for (int k = 0; k < KTOT; k++) {
                    float a = rd_a(g_x16, KT1, m, k);
                    accg += a * rd_b8(g_wgu8, KT1, nb, cc, k, BTILE1R, 128);
                    accu += a * rd_b8(g_wgu8, KT1, nb, 128 + cc, k, BTILE1R, 128);
                }
                float g = accg * S[n0 + cc], u = accu * S[INTER + n0 + cc];
                float hv = g / (1.0f + __expf(-g)) * u;
                const int col = n0 + cc;
                const int mm = m & 511;
                const int rank2 = (mm >> 7) & 1;
                const int wr2 = ((mm >> 8) << 7) | (mm & 127);
                char* p = reinterpret_cast<char*>(g_h16)
                        + ((size_t)(m >> 9) * KT2 + (col >> 6)) * ATILE + rank2 * 32768
                        + swz((uint32_t)(wr2 * 128 + ((col & 63) >> 3) * 16)) + (col & 7) * 2;
                *reinterpret_cast<__half*>(p) = __float2half_rn(hv);
            } else {
                float acc = 0.f;
                for (int k = 0; k < KTOT; k++)
                    acc += rd_a(g_h16, KT2, m, k) * rd_b8(g_wd8, KT2, nb, cc, k, BTILE2R, 112);
                Out[(size_t)m * HIDDEN + n0 + cc] = acc * S[n0 + cc];
            }
        }
    }
#endif
}

// ---------------------------------------------------------------------------
// launch
// ---------------------------------------------------------------------------
extern "C" void kernel_launch(void* const* d_in, const int* in_sizes, int n_in,
                              void* d_out, int out_size)
{
    const float* x = nullptr; const float* w_gu = nullptr; const float* s_gu = nullptr;
    const float* w_d = nullptr; const float* s_d = nullptr;
    for (int i = 0; i < n_in; i++) {
        long long sz = in_sizes[i];
        const float* p = (const float*)d_in[i];
        if      (sz == (long long)TOKENS * HIDDEN)    x    = p;
        else if (sz == (long long)2 * INTER * HIDDEN) w_gu = p;
        else if (sz == (long long)2 * INTER)          s_gu = p;
        else if (sz == (long long)HIDDEN * INTER)     w_d  = p;
        else if (sz == (long long)HIDDEN)             s_d  = p;
    }
    float* out = (float*)d_out;

    constexpr int SMEM0 = 1024 + NSTG * (A_BYTES + BB1 + BR1);  // 230,400
    constexpr int SMEM1 = 1024 + NSTG * (A_BYTES + BB2 + BR2);  // 218,112
    cudaFuncSetAttribute(mlp_gemm<0>, cudaFuncAttributeMaxDynamicSharedMemorySize, SMEM0);
    cudaFuncSetAttribute(mlp_gemm<1>, cudaFuncAttributeMaxDynamicSharedMemorySize, SMEM1);

    // prep: zero converter state + out, w_gu stripes [0,18), x
    conv_prep<<<(PRE_CHUNKS + X_CHUNKS + OUT_CHUNKS + 255) / 256, 256>>>(w_gu, x, out);

    // GEMM1: gate_up + SiLU*Mul -> g_h16; converter warps finish w_gu + w_d
    mlp_gemm<0><<<dim3(2 * NPAIRS, 1), THREADS, SMEM0>>>(s_gu, nullptr, w_gu, w_d);

    // GEMM2: down -> out (exact 512 kt-units per pair, red-add boundaries)
    mlp_gemm<1><<<dim3(2 * NPAIRS, 1), THREADS, SMEM1>>>(s_d, out, nullptr, nullptr);
}

// round 16
// speedup vs baseline: 1.0225x; 1.0225x over previous
#include <cuda_runtime.h>
#include <cuda_fp16.h>
#include <cuda_fp8.h>
#include <cstdint>

// ---------------------------------------------------------------------------
// Qwen2 FP8 MLP, fp16 tcgen05 cg2 persistent + fp8 weight delivery.
//   R16: exact K-balanced GEMM2 (512 kt-units/pair; 74*512 == 128*296) with
//   DETERMINISTIC partial combine: head segment (done FIRST in its pair)
//   stores raw fp32 partial to g_part[T] + release flag; tail segment (done
//   LAST in its pair) acquires the flag, adds, scales, stores out once.
//   No atomics on out, no zero-init. GEMM1/dynamic converter = R14.
// ---------------------------------------------------------------------------

#if defined(__CUDA_ARCH_FEAT_SM103_ALL) || defined(__CUDA_ARCH_FEAT_SM100_ALL) || defined(__CUDA_ARCH_SPECIFIC__)
#define USE_TCGEN05 1
#else
#define USE_TCGEN05 0
#endif

namespace {
constexpr int HIDDEN = 3584;
constexpr int INTER  = 18944;
constexpr int TOKENS = 4096;

constexpr int KC      = 64;
constexpr int NSTG    = 4;
constexpr int THREADS = 448;      // w0 MMA, w1 prod, w2-3 dequant, w4-11 epi, w12-13 conv
constexpr int NPAIRS  = 74;

constexpr int A_BYTES = 32768;
constexpr int ATILE   = 65536;

constexpr int KT1 = HIDDEN / KC;              // 56
constexpr int KT2 = INTER  / KC;              // 296

constexpr int NB1      = INTER / 128;         // 148
constexpr int BB1      = 16384;
constexpr int BR1      = 8192;
constexpr int BTILE1R  = 16384;
constexpr int NT1      = (TOKENS / 512) * NB1;

constexpr int N2       = 224;
constexpr int NB2      = HIDDEN / N2;         // 16
constexpr int BB2      = 14336;
constexpr int BR2      = 7168;
constexpr int BTILE2R  = 14336;
constexpr int NTILE2   = (TOKENS / 512) * NB2;   // 128

constexpr int UNITS_PP = 512;                 // 74*512 == 128*296 exactly

constexpr int PRECONV   = 18;
constexpr int PRE_CHUNKS = PRECONV * KT1 * 1024;
constexpr int X_CHUNKS   = (TOKENS / 512) * KT1 * 4096;
constexpr int WGU_UNITS  = (NB1 - PRECONV) * KT1;
constexpr int WD_UNITS   = NB2 * KT2;
constexpr int TOTAL_UNITS = WGU_UNITS + WD_UNITS;
}

__device__ __half   g_x16[(size_t)(TOKENS / 512) * KT1 * (ATILE / 2)];
__device__ uint8_t  g_wgu8[(size_t)NB1 * KT1 * BTILE1R];
__device__ uint8_t  g_wd8 [(size_t)NB2 * KT2 * BTILE2R];
__device__ __half   g_h16[(size_t)(TOKENS / 512) * KT2 * (ATILE / 2)];

__device__ float    g_part[(size_t)NTILE2 * 512 * N2];   // raw partial scratch
__device__ uint32_t g_pflag[NTILE2];                     // 16 arrivals when ready
__device__ uint32_t g_uctr;
__device__ uint32_t g_wdone[NB1];

__host__ __device__ __forceinline__ uint32_t swz(uint32_t off) {
    return off ^ ((off >> 3) & 0x70);
}

__device__ __forceinline__ uint32_t pack_e4m3_4(float f0, float f1, float f2, float f3) {
    uint32_t w;
    asm("{\n\t.reg .b16 p0, p1;\n\t"
        "cvt.rn.satfinite.e4m3x2.f32 p0, %2, %1;\n\t"
        "cvt.rn.satfinite.e4m3x2.f32 p1, %4, %3;\n\t"
        "mov.b32 %0, {p0, p1};\n\t}"
        : "=r"(w) : "f"(f0), "f"(f1), "f"(f2), "f"(f3));
    return w;
}
__device__ __forceinline__ void fp8x4_to_h2x2(uint32_t w, uint32_t& o0, uint32_t& o1) {
    asm("{\n\t.reg .b16 lo, hi;\n\t"
        "mov.b32 {lo, hi}, %2;\n\t"
        "cvt.rn.f16x2.e4m3x2 %0, lo;\n\t"
        "cvt.rn.f16x2.e4m3x2 %1, hi;\n\t}"
        : "=r"(o0), "=r"(o1) : "r"(w));
}
__device__ __forceinline__ void stg_cg_v4(void* p, uint4 v) {
    asm volatile("st.global.cg.v4.u32 [%0], {%1,%2,%3,%4};"
                 :: "l"(p), "r"(v.x), "r"(v.y), "r"(v.z), "r"(v.w) : "memory");
}

__device__ __forceinline__ void conv_wgu8_chunk(const float* __restrict__ src,
                                                int tile, int c) {
    const int tr = c >> 2;
    const int ch = c & 3;
    const int kt = tile % KT1;
    const int nb = tile / KT1;
    const int grow = (tr < 128) ? (nb * 128 + tr) : (INTER + nb * 128 + (tr - 128));
    const float* s = src + (size_t)grow * HIDDEN + kt * KC + ch * 16;
    uint32_t w[4];
    #pragma unroll
    for (int q = 0; q < 4; q++) {
        float4 f = reinterpret_cast<const float4*>(s)[q];
        w[q] = pack_e4m3_4(f.x, f.y, f.z, f.w);
    }
    uint8_t* dst = g_wgu8 + (size_t)tile * BTILE1R
                 + (tr >> 7) * BR1 + (tr & 127) * 64 + ch * 16;
    stg_cg_v4(dst, make_uint4(w[0], w[1], w[2], w[3]));
}

__device__ __forceinline__ void conv_wd8_chunk(const float* __restrict__ src, int gid) {
    const int tile = gid / 896;
    const int c    = gid % 896;
    const int tr   = c >> 2;
    const int ch   = c & 3;
    const int kt   = tile % KT2;
    const int bb   = tile / KT2;
    const int grow = bb * N2 + tr;
    const float* s = src + (size_t)grow * INTER + kt * KC + ch * 16;
    uint32_t w[4];
    #pragma unroll
    for (int q = 0; q < 4; q++) {
        float4 f = reinterpret_cast<const float4*>(s)[q];
        w[q] = pack_e4m3_4(f.x, f.y, f.z, f.w);
    }
    const int half = tr / 112;
    const int wr   = tr - half * 112;
    uint8_t* dst = g_wd8 + (size_t)tile * BTILE2R + half * BR2 + wr * 64 + ch * 16;
    *reinterpret_cast<uint4*>(dst) = make_uint4(w[0], w[1], w[2], w[3]);
}

// ---------------------------------------------------------------------------
// prep: zero converter/flag state, w_gu stripes [0, PRECONV), x
// ---------------------------------------------------------------------------
__global__ void __launch_bounds__(256) conv_prep(const float* __restrict__ w_gu,
                                                 const float* __restrict__ x) {
    int gid = blockIdx.x * 256 + threadIdx.x;
    if (gid == 0) g_uctr = 0;
    if (gid >= 1 && gid <= NB1) g_wdone[gid - 1] = 0;
    if (gid >= 256 && gid < 256 + NTILE2) g_pflag[gid - 256] = 0;

    if (gid < PRE_CHUNKS) {
        conv_wgu8_chunk(w_gu, gid >> 10, gid & 1023);
        return;
    }
    gid -= PRE_CHUNKS;
    if (gid < X_CHUNKS) {
        const int tile = gid >> 12;
        const int c    = gid & 4095;
        const int sr   = c >> 3;
        const int ch   = c & 7;
        const int kt   = tile % KT1;
        const int mb   = tile / KT1;
        const int rank = sr >> 8;
        const int wr   = sr & 255;
        const int m    = mb * 512 + (wr >> 7) * 256 + rank * 128 + (wr & 127);
        const float* s = x + (size_t)m * HIDDEN + kt * KC + ch * 8;
        float4 a = *reinterpret_cast<const float4*>(s);
        float4 b = *reinterpret_cast<const float4*>(s + 4);
        __half2 p0 = __floats2half2_rn(a.x, a.y);
        __half2 p1 = __floats2half2_rn(a.z, a.w);
        __half2 p2 = __floats2half2_rn(b.x, b.y);
        __half2 p3 = __floats2half2_rn(b.z, b.w);
        uint4 v = make_uint4(*reinterpret_cast<uint32_t*>(&p0),
                             *reinterpret_cast<uint32_t*>(&p1),
                             *reinterpret_cast<uint32_t*>(&p2),
                             *reinterpret_cast<uint32_t*>(&p3));
        char* dst = reinterpret_cast<char*>(g_x16) + (size_t)tile * ATILE
                  + rank * 32768 + swz((uint32_t)(wr * 128 + ch * 16));
        *reinterpret_cast<uint4*>(dst) = v;
    }
}

// ---------------------------------------------------------------------------
// device helpers
// ---------------------------------------------------------------------------
#if USE_TCGEN05
__device__ __forceinline__ bool elect_one() {
    uint32_t p;
    asm volatile("{\n\t.reg .pred p;\n\telect.sync _|p, 0xFFFFFFFF;\n\t"
                 "selp.b32 %0, 1, 0, p;\n\t}" : "=r"(p));
    return p != 0;
}
__device__ __forceinline__ uint32_t ctarank() {
    uint32_t r;
    asm("mov.u32 %0, %%cluster_ctarank;" : "=r"(r));
    return r;
}
__device__ __forceinline__ void mbar_init(uint32_t addr, uint32_t count) {
    asm volatile("mbarrier.init.shared.b64 [%0], %1;" :: "r"(addr), "r"(count) : "memory");
}
__device__ __forceinline__ void mbar_wait(uint32_t addr, uint32_t parity) {
    asm volatile(
        "{\n\t.reg .pred P;\n\t"
        "WL_%=:\n\t"
        "mbarrier.try_wait.parity.acquire.cta.shared::cta.b64 P, [%0], %1, 0x989680;\n\t"
        "@P bra.uni WD_%=;\n\t"
        "bra.uni WL_%=;\n\t"
        "WD_%=:\n\t}"
        :: "r"(addr), "r"(parity) : "memory");
}
__device__ __forceinline__ void mbar_expect_tx(uint32_t addr, uint32_t bytes) {
    asm volatile("mbarrier.arrive.expect_tx.shared.b64 _, [%0], %1;"
                 :: "r"(addr), "r"(bytes) : "memory");
}
__device__ __forceinline__ void mbar_arrive(uint32_t addr) {
    asm volatile("mbarrier.arrive.shared.b64 _, [%0];" :: "r"(addr) : "memory");
}
__device__ __forceinline__ void mbar_arrive_remote(uint32_t local_addr, uint32_t target_rank) {
    asm volatile(
        "{\n\t.reg .b32 ra;\n\t"
        "mapa.shared::cluster.u32 ra, %0, %1;\n\t"
        "mbarrier.arrive.shared::cluster.b64 _, [ra];\n\t}"
        :: "r"(local_addr), "r"(target_rank) : "memory");
}
__device__ __forceinline__ void bulk_g2s(uint32_t dst, const void* src, uint32_t bytes,
                                         uint32_t mbar) {
    asm volatile(
        "cp.async.bulk.shared::cluster.global.mbarrier::complete_tx::bytes "
        "[%0], [%1], %2, [%3];"
        :: "r"(dst), "l"(src), "r"(bytes), "r"(mbar) : "memory");
}
__device__ __forceinline__ void tc_alloc_cg2(uint32_t dst_smem, uint32_t ncols) {
    asm volatile("tcgen05.alloc.cta_group::2.sync.aligned.shared::cta.b32 [%0], %1;"
                 :: "r"(dst_smem), "r"(ncols) : "memory");
}
__device__ __forceinline__ void tc_relinquish_cg2() {
    asm volatile("tcgen05.relinquish_alloc_permit.cta_group::2.sync.aligned;");
}
__device__ __forceinline__ void tc_dealloc_cg2(uint32_t tmem, uint32_t ncols) {
    asm volatile("tcgen05.dealloc.cta_group::2.sync.aligned.b32 %0, %1;"
                 :: "r"(tmem), "r"(ncols));
}
__device__ __forceinline__ void tc_commit_mc_cg2(uint32_t mbar, uint16_t mask) {
    asm volatile(
        "tcgen05.commit.cta_group::2.mbarrier::arrive::one.shared::cluster.multicast::cluster.b64 "
        "[%0], %1;"
        :: "r"(mbar), "h"(mask) : "memory");
}
__device__ __forceinline__ void tc_wait_ld() {
    asm volatile("tcgen05.wait::ld.sync.aligned;" ::: "memory");
}
__device__ __forceinline__ uint64_t sdesc(uint32_t addr) {
    return ((uint64_t)((addr >> 4) & 0x3FFF))
         | (1ULL  << 16) | (64ULL << 32) | (1ULL << 46) | (2ULL << 61);
}
__device__ __forceinline__ void mma_f16_ss_cg2(uint32_t d_tmem, uint64_t ad, uint64_t bd,
                                               uint32_t idesc, uint32_t enable_d) {
    asm volatile(
        "{\n\t.reg .pred p;\n\t"
        "setp.ne.u32 p, %4, 0;\n\t"
        "tcgen05.mma.cta_group::2.kind::f16 [%0], %1, %2, %3, "
        "{%5,%5,%5,%5,%5,%5,%5,%5}, p;\n\t}"
        :: "r"(d_tmem), "l"(ad), "l"(bd), "r"(idesc), "r"(enable_d), "r"(0u)
        : "memory");
}
__device__ __forceinline__ void ldtm32(uint32_t* r, uint32_t ta) {
    asm volatile(
        "tcgen05.ld.sync.aligned.32x32b.x32.b32 "
        "{%0,%1,%2,%3,%4,%5,%6,%7,%8,%9,%10,%11,%12,%13,%14,%15,"
        "%16,%17,%18,%19,%20,%21,%22,%23,%24,%25,%26,%27,%28,%29,%30,%31}, [%32];"
        : "=r"(r[0]),  "=r"(r[1]),  "=r"(r[2]),  "=r"(r[3]),
          "=r"(r[4]),  "=r"(r[5]),  "=r"(r[6]),  "=r"(r[7]),
          "=r"(r[8]),  "=r"(r[9]),  "=r"(r[10]), "=r"(r[11]),
          "=r"(r[12]), "=r"(r[13]), "=r"(r[14]), "=r"(r[15]),
          "=r"(r[16]), "=r"(r[17]), "=r"(r[18]), "=r"(r[19]),
          "=r"(r[20]), "=r"(r[21]), "=r"(r[22]), "=r"(r[23]),
          "=r"(r[24]), "=r"(r[25]), "=r"(r[26]), "=r"(r[27]),
          "=r"(r[28]), "=r"(r[29]), "=r"(r[30]), "=r"(r[31])
        : "r"(ta));
}
#endif

// fallback read helpers
__device__ __forceinline__ float rd_a(const __half* buf, int KT, int m, int k) {
    const int mb = m >> 9, mm = m & 511;
    const int rank = (mm >> 7) & 1;
    const int wr = ((mm >> 8) << 7) | (mm & 127);
    const char* p = reinterpret_cast<const char*>(buf)
                  + ((size_t)mb * KT + (k >> 6)) * ATILE + rank * 32768
                  + swz((uint32_t)(wr * 128 + ((k & 63) >> 3) * 16)) + (k & 7) * 2;
    return __half2float(*reinterpret_cast<const __half*>(p));
}
__device__ __forceinline__ float rd_b8(const uint8_t* buf, int KT, int tile_b, int tr, int k,
                                       int tile_bytes, int half_rows) {
    const int half = tr / half_rows;
    const int wr   = tr - half * half_rows;
    const uint8_t* p = buf + ((size_t)tile_b * KT + (k >> 6)) * tile_bytes
                     + half * (tile_bytes / 2) + wr * 64 + (k & 63);
    __nv_fp8_e4m3 v;
    *reinterpret_cast<uint8_t*>(&v) = *p;
    return float(v);
}

// ---------------------------------------------------------------------------
// Persistent GEMM. grid (148,1,1), cluster (2,1,1), 448 threads.
// MODE 0: 16 tiles/pair mb-major + chip-wide dynamic converter (warps 12-13).
// MODE 1: 512 kt-units/pair, segments ordered [head partial, fulls, tail
//         finalizer]; head stores raw partial + flag, tail combines.
// ---------------------------------------------------------------------------
template <int MODE>
__global__ void __launch_bounds__(THREADS, 1) __cluster_dims__(2, 1, 1)
mlp_gemm(const float* __restrict__ S, float* __restrict__ Out,
         const float* __restrict__ Wgu32, const float* __restrict__ Wd32)
{
    constexpr int KT      = (MODE == 0) ? KT1 : KT2;
    constexpr int NMMA    = (MODE == 0) ? 256 : N2;
    constexpr int BBYTES  = (MODE == 0) ? BB1 : BB2;
    constexpr int BRAW    = (MODE == 0) ? BR1 : BR2;
    constexpr int BTILER  = (MODE == 0) ? BTILE1R : BTILE2R;
    constexpr int STG_B   = A_BYTES + BBYTES + BRAW;
    constexpr int DQU     = (MODE == 0) ? 8 : 7;
    const int pair = blockIdx.x >> 1;
    const int ntp  = NT1 / NPAIRS;   // MODE 0 tiles per pair (16)

    extern __shared__ char smem[];
    const int t    = threadIdx.x;
    const int wid  = t >> 5;
    const int lane = t & 31;

#if USE_TCGEN05
    constexpr uint32_t IDESC = (1u << 4) | ((uint32_t)(NMMA / 8) << 17) | (16u << 24);

    const uint32_t sbase     = (uint32_t)__cvta_generic_to_shared(smem);
    const uint32_t tptr_addr = sbase;
    const uint32_t bar_full  = sbase + 8;
    const uint32_t bar_empty = bar_full + NSTG * 8;
    const uint32_t bar_deq   = bar_empty + NSTG * 8;
    const uint32_t bar_done  = bar_deq + NSTG * 8;
    const uint32_t bar_elo   = bar_done + 8;
    const uint32_t bar_ehi   = bar_done + 16;
    const uint32_t data_u    = (sbase + 256 + 1023) & ~1023u;
    const uint32_t rank      = ctarank();

    // MODE 1: segments ordered [head(role1), fulls(role0), tail(role2)]
    int segT[3], segK0[3], segK1[3], segRole[3], nseg = 0;
    if (MODE == 1) {
        const int ustart = UNITS_PP * pair, uend = ustart + UNITS_PP;
        const int Tf = ustart / KT2, Tl = (uend - 1) / KT2;
        const int k1l = uend - Tl * KT2;
        if (k1l < KT2) {                                   // head partial
            segT[nseg] = Tl; segK0[nseg] = 0; segK1[nseg] = k1l; segRole[nseg] = 1; nseg++;
        }
        for (int T = Tf; T <= Tl; T++) {                   // full tiles
            const int k0 = (ustart > T * KT2) ? (ustart - T * KT2) : 0;
            const int k1 = (uend - T * KT2 > KT2) ? KT2 : (uend - T * KT2);
            if (k0 == 0 && k1 == KT2) {
                segT[nseg] = T; segK0[nseg] = 0; segK1[nseg] = KT2; segRole[nseg] = 0; nseg++;
            }
        }
        const int k0f = ustart - Tf * KT2;
        if (k0f > 0) {                                     // tail finalizer
            segT[nseg] = Tf; segK0[nseg] = k0f; segK1[nseg] = KT2; segRole[nseg] = 2; nseg++;
        }
    }

    auto tile_mb_nb = [&](int tl, int& mb, int& nb) {      // MODE 0 map
        const int idx = tl * NPAIRS + pair;
        mb = idx & 7; nb = idx >> 3;
    };

    if (wid == 0) { tc_alloc_cg2(tptr_addr, 512); tc_relinquish_cg2(); }
    if (t == 0) {
        for (int s = 0; s < NSTG; s++) {
            mbar_init(bar_full  + s * 8, 1);
            mbar_init(bar_empty + s * 8, 1);
            mbar_init(bar_deq   + s * 8, 4);
        }
        mbar_init(bar_done, 1);
        mbar_init(bar_elo, 8);
        mbar_init(bar_ehi, 8);
    }
    __syncthreads();
    asm volatile("barrier.cluster.arrive.aligned;" ::: "memory");
    asm volatile("barrier.cluster.wait.aligned;"   ::: "memory");

    uint32_t tmem;
    asm volatile("ld.shared.b32 %0, [%1];" : "=r"(tmem) : "r"(tptr_addr));

    const char*    Abuf = reinterpret_cast<const char*>((MODE == 0) ? g_x16 : g_h16);
    const uint8_t* Bbuf = (MODE == 0) ? g_wgu8 : g_wd8;

    if (t == 32) {
        // ---------------- TMA producer ----------------
        uint32_t g = 0;
        if (MODE == 0) {
            for (int tl = 0; tl < ntp; tl++) {
                int mb, nb; tile_mb_nb(tl, mb, nb);
                if (nb >= PRECONV) {
                    uint32_t v;
                    const uint32_t* fp = &g_wdone[nb];
                    do {
                        asm volatile("ld.acquire.gpu.global.u32 %0, [%1];"
                                     : "=r"(v) : "l"(fp) : "memory");
                    } while (v < (uint32_t)KT1);
                }
                const char*    a_base = Abuf + (size_t)mb * KT * ATILE + rank * 32768;
                const uint8_t* b_base = Bbuf + (size_t)nb * KT * BTILER + rank * BRAW;
                for (int kt = 0; kt < KT; kt++, g++) {
                    const uint32_t s = g & (NSTG - 1);
                    if (g >= NSTG) mbar_wait(bar_empty + s * 8, ((g >> 2) - 1) & 1);
                    const uint32_t As = data_u + s * STG_B;
                    mbar_expect_tx(bar_full + s * 8, A_BYTES + BRAW);
                    bulk_g2s(As, a_base + (size_t)kt * ATILE, A_BYTES, bar_full + s * 8);
                    bulk_g2s(As + A_BYTES + BBYTES, b_base + (size_t)kt * BTILER, BRAW,
                             bar_full + s * 8);
                }
            }
        } else {
            for (int sg = 0; sg < nseg; sg++) {
                const int mb = segT[sg] & 7, nb = segT[sg] >> 3;
                const char*    a_base = Abuf + (size_t)mb * KT * ATILE + rank * 32768;
                const uint8_t* b_base = Bbuf + (size_t)nb * KT * BTILER + rank * BRAW;
                for (int kt = segK0[sg]; kt < segK1[sg]; kt++, g++) {
                    const uint32_t s = g & (NSTG - 1);
                    if (g >= NSTG) mbar_wait(bar_empty + s * 8, ((g >> 2) - 1) & 1);
                    const uint32_t As = data_u + s * STG_B;
                    mbar_expect_tx(bar_full + s * 8, A_BYTES + BRAW);
                    bulk_g2s(As, a_base + (size_t)kt * ATILE, A_BYTES, bar_full + s * 8);
                    bulk_g2s(As + A_BYTES + BBYTES, b_base + (size_t)kt * BTILER, BRAW,
                             bar_full + s * 8);
                }
            }
        }
    } else if (wid == 2 || wid == 3) {
        // ---------------- dequant warps ----------------
        const int wt = t - 64;
        const uint32_t total = (MODE == 0) ? (uint32_t)ntp * KT : (uint32_t)UNITS_PP;
        for (uint32_t g = 0; g < total; g++) {
            const uint32_t s = g & (NSTG - 1);
            mbar_wait(bar_full + s * 8, (g >> 2) & 1);
            const uint32_t As  = data_u + s * STG_B;
            const uint32_t dst = As + A_BYTES;
            const uint32_t raw = dst + BBYTES;
            #pragma unroll
            for (int j = 0; j < DQU; j++) {
                const int u   = wt + 64 * j;
                const int row = u >> 2;
                const int ch  = u & 3;
                uint4 r;
                asm volatile("ld.shared.v4.u32 {%0,%1,%2,%3}, [%4];"
                             : "=r"(r.x), "=r"(r.y), "=r"(r.z), "=r"(r.w)
                             : "r"(raw + row * 64 + ch * 16));
                uint32_t o0, o1, o2, o3, o4, o5, o6, o7;
                fp8x4_to_h2x2(r.x, o0, o1);
                fp8x4_to_h2x2(r.y, o2, o3);
                fp8x4_to_h2x2(r.z, o4, o5);
                fp8x4_to_h2x2(r.w, o6, o7);
                const uint32_t ob = (uint32_t)(row * 128 + ch * 32);
                asm volatile("st.shared.v4.b32 [%0], {%1,%2,%3,%4};"
                             :: "r"(dst + swz(ob)), "r"(o0), "r"(o1), "r"(o2), "r"(o3)
                             : "memory");
                asm volatile("st.shared.v4.b32 [%0], {%1,%2,%3,%4};"
                             :: "r"(dst + swz(ob + 16)), "r"(o4), "r"(o5), "r"(o6), "r"(o7)
                             : "memory");
            }
            asm volatile("fence.proxy.async.shared::cta;" ::: "memory");
            if (elect_one()) {
                if (rank == 0) mbar_arrive(bar_deq + s * 8);
                else           mbar_arrive_remote(bar_deq + s * 8, 0);
            }
        }
    } else if (wid == 0 && rank == 0) {
        // ---------------- MMA issuer (leader) ----------------
        if (elect_one()) {
            uint32_t g = 0;
            const int nloops = (MODE == 0) ? ntp : nseg;
            for (int li = 0; li < nloops; li++) {
                const int k0 = (MODE == 0) ? 0  : segK0[li];
                const int k1 = (MODE == 0) ? KT : segK1[li];
                for (int kt = k0; kt < k1; kt++, g++) {
                    const uint32_t s = g & (NSTG - 1);
                    mbar_wait(bar_deq + s * 8, (g >> 2) & 1);
                    const uint32_t As = data_u + s * STG_B;
                    const uint64_t ad0 = sdesc(As);
                    const uint64_t ad1 = sdesc(As + 16384);
                    const uint64_t bd  = sdesc(As + A_BYTES);
                    if (kt == k0) {
                        if (li > 0) mbar_wait(bar_elo, (li - 1) & 1);
                        #pragma unroll
                        for (int kk = 0; kk < 4; kk++)
                            mma_f16_ss_cg2(tmem, ad0 + 2 * kk, bd + 2 * kk, IDESC, kk > 0);
                        if (li > 0) mbar_wait(bar_ehi, (li - 1) & 1);
                        #pragma unroll
                        for (int kk = 0; kk < 4; kk++)
                            mma_f16_ss_cg2(tmem + NMMA, ad1 + 2 * kk, bd + 2 * kk, IDESC, kk > 0);
                    } else {
                        #pragma unroll
                        for (int kk = 0; kk < 4; kk++) {
                            mma_f16_ss_cg2(tmem,        ad0 + 2 * kk, bd + 2 * kk, IDESC, 1);
                            mma_f16_ss_cg2(tmem + NMMA, ad1 + 2 * kk, bd + 2 * kk, IDESC, 1);
                        }
                    }
                    tc_commit_mc_cg2(bar_empty + s * 8, (uint16_t)0x3);
                }
                tc_commit_mc_cg2(bar_done, (uint16_t)0x3);
            }
        }
    } else if (wid >= 4 && wid < 12) {
        // ---------------- epilogue warps ----------------
        const int mh = (wid >> 2) - 1;
        const int sp = wid & 3;
        const uint32_t tbase = tmem + mh * NMMA;
        const uint32_t ebar  = (mh == 0) ? bar_elo : bar_ehi;
        const int nloops = (MODE == 0) ? ntp : nseg;
        for (int li = 0; li < nloops; li++) {
            int mb, nb, role = 0, T = 0;
            if (MODE == 0) tile_mb_nb(li, mb, nb);
            else {
                T = segT[li]; mb = T & 7; nb = T >> 3; role = segRole[li];
            }
            mbar_wait(bar_done, li & 1);
            asm volatile("tcgen05.fence::after_thread_sync;" ::: "memory");
            const int ml = mh * 256 + (int)rank * 128 + sp * 32 + lane;   // local row
            const int m  = mb * 512 + ml;

            if (MODE == 0) {
                const int n0 = nb * 128;
                const int mm = m & 511;
                const int rank2 = (mm >> 7) & 1;
                const int wr2 = ((mm >> 8) << 7) | (mm & 127);
                char* hb = reinterpret_cast<char*>(g_h16)
                         + (size_t)(m >> 9) * KT2 * ATILE + rank2 * 32768;
                #pragma unroll
                for (int c = 0; c < 4; c++) {
                    const int cb = c * 32;
                    uint32_t gr[32], ur[32];
                    ldtm32(gr, tbase + cb);
                    ldtm32(ur, tbase + 128 + cb);
                    tc_wait_ld();
                    if (c == 3) {
                        if (elect_one()) mbar_arrive_remote(ebar, 0);
                    }
                    uint32_t oh[16];
                    #pragma unroll
                    for (int p = 0; p < 16; p++) {
                        const int i = 2 * p;
                        const int n = n0 + cb + i;
                        float g0 = __uint_as_float(gr[i])     * __ldg(S + n);
                        float g1 = __uint_as_float(gr[i + 1]) * __ldg(S + n + 1);
                        float u0 = __uint_as_float(ur[i])     * __ldg(S + INTER + n);
                        float u1 = __uint_as_float(ur[i + 1]) * __ldg(S + INTER + n + 1);
                        float h0 = __fdividef(g0, 1.0f + __expf(-g0)) * u0;
                        float h1 = __fdividef(g1, 1.0f + __expf(-g1)) * u1;
                        __half2 ph = __floats2half2_rn(h0, h1);
                        oh[p] = *reinterpret_cast<uint32_t*>(&ph);
                    }
                    #pragma unroll
                    for (int q = 0; q < 4; q++) {
                        const int col = n0 + cb + q * 8;
                        char* tb = hb + (size_t)(col >> 6) * ATILE;
                        const uint32_t off = swz((uint32_t)(wr2 * 128 + ((col & 63) >> 3) * 16));
                        *reinterpret_cast<uint4*>(tb + off) =
                            make_uint4(oh[4 * q], oh[4 * q + 1], oh[4 * q + 2], oh[4 * q + 3]);
                    }
                }
            } else {
                const int n0 = nb * N2;
                float* op = Out + (size_t)m * HIDDEN + n0;
                float* pp = g_part + ((size_t)T * 512 + ml) * N2;
                if (role == 2) {
                    // finalizer: wait for partner's partial
                    uint32_t v;
                    const uint32_t* fp = &g_pflag[T];
                    do {
                        asm volatile("ld.acquire.gpu.global.u32 %0, [%1];"
                                     : "=r"(v) : "l"(fp) : "memory");
                    } while (v < 16u);
                }
                #pragma unroll
                for (int c = 0; c < 7; c++) {
                    const int cb = c * 32;
                    uint32_t dr[32];
                    ldtm32(dr, tbase + cb);
                    tc_wait_ld();
                    if (c == 6) {
                        if (elect_one()) mbar_arrive_remote(ebar, 0);
                    }
                    #pragma unroll
                    for (int q = 0; q < 8; q++) {
                        float r[4];
                        #pragma unroll
                        for (int j = 0; j < 4; j++)
                            r[j] = __uint_as_float(dr[q * 4 + j]);
                        if (role == 1) {
                            // head: raw partial to scratch
                            reinterpret_cast<float4*>(pp + cb)[q] =
                                make_float4(r[0], r[1], r[2], r[3]);
                        } else {
                            if (role == 2) {
                                float4 pv = reinterpret_cast<const float4*>(pp + cb)[q];
                                r[0] += pv.x; r[1] += pv.y; r[2] += pv.z; r[3] += pv.w;
                            }
                            #pragma unroll
                            for (int j = 0; j < 4; j++)
                                r[j] *= __ldg(S + n0 + cb + q * 4 + j);
                            reinterpret_cast<float4*>(op + cb)[q] =
                                make_float4(r[0], r[1], r[2], r[3]);
                        }
                    }
                }
                if (role == 1) {
                    // release partial to the finalizer (one arrive per warp)
                    if (elect_one()) {
                        uint32_t* fp = &g_pflag[T];
                        asm volatile("red.release.gpu.global.add.u32 [%0], %1;"
                                     :: "l"(fp), "r"(1u) : "memory");
                    }
                }
            }
        }
    } else if (MODE == 0 && wid >= 12) {
        // ---------------- chip-wide dynamic converter ----------------
        for (;;) {
            uint32_t u;
            if (lane == 0) u = atomicAdd(&g_uctr, 1u);
            u = __shfl_sync(0xFFFFFFFFu, u, 0);
            if (u >= (uint32_t)TOTAL_UNITS) break;
            if (u < (uint32_t)WGU_UNITS) {
                const int tile = PRECONV * KT1 + (int)u;
                const int nb   = tile / KT1;
                #pragma unroll 4
                for (int j = 0; j < 32; j++)
                    conv_wgu8_chunk(Wgu32, tile, lane + 32 * j);
                __syncwarp();
                if (lane == 0) {
                    uint32_t* dp = &g_wdone[nb];
                    asm volatile("red.release.gpu.global.add.u32 [%0], %1;"
                                 :: "l"(dp), "r"(1u) : "memory");
                }
            } else {
                const int t2 = (int)u - WGU_UNITS;
                #pragma unroll 4
                for (int j = 0; j < 28; j++)
                    conv_wd8_chunk(Wd32, t2 * 896 + lane + 32 * j);
            }
        }
    }

    __syncthreads();
    if (wid == 0) tc_dealloc_cg2(tmem, 512);
    asm volatile("barrier.cluster.arrive.aligned;" ::: "memory");
    asm volatile("barrier.cluster.wait.aligned;"   ::: "memory");

#else
    // non-103a compile pass only (never selected at runtime on GB300)
    (void)smem; (void)lane;
    const int rankf = blockIdx.x & 1;
    constexpr int KTOT = (MODE == 0) ? HIDDEN : INTER;
    constexpr int NCOL = (MODE == 0) ? 128 : N2;
    const int ntpf = (MODE == 0) ? ntp
                                 : ((pair < NTILE2 - NPAIRS) ? 2 : 1);
    if (MODE == 0) {
        for (int tl = 0; tl < ntpf; tl++) {
            const int idx = tl * NPAIRS + pair;
            const int nb = idx >> 3;
            for (int u = t; u < KT1 * 1024; u += THREADS)
                conv_wgu8_chunk(Wgu32, nb * KT1 + (u >> 10), u & 1023);
        }
        for (int g = (int)blockIdx.x * THREADS + t; g < NB2 * KT2 * 896;
             g += 148 * THREADS)
            conv_wd8_chunk(Wd32, g);
        __syncthreads();
    }
    for (int tl = 0; tl < ntpf; tl++) {
        const int idx = tl * NPAIRS + pair;
        const int mb = idx & 7, nb = idx >> 3;
        const int n0 = nb * NCOL;
        for (int o = t; o < 256 * NCOL; o += THREADS) {
            const int rr = o / NCOL, cc = o % NCOL;
            const int m = mb * 512 + (rr >> 7) * 256 + rankf * 128 + (rr & 127);
            if (MODE == 0) {
                float accg = 0.f, accu = 0.f;
                for (int k = 0; k < KTOT; k++) {
                    float a = rd_a(g_x16, KT1, m, k);
                    accg += a * rd_b8(g_wgu8, KT1, nb, cc, k, BTILE1R, 128);
                    accu += a * rd_b8(g_wgu8, KT1, nb, 128 + cc, k, BTILE1R, 128);
                }
                float g = accg * S[n0 + cc], u = accu * S[INTER + n0 + cc];
                float hv = g / (1.0f + __expf(-g)) * u;
                const int col = n0 + cc;
                const int mm = m & 511;
                const int rank2 = (mm >> 7) & 1;
                const int wr2 = ((mm >> 8) << 7) | (mm & 127);
                char* p = reinterpret_cast<char*>(g_h16)
                        + ((size_t)(m >> 9) * KT2 + (col >> 6)) * ATILE + rank2 * 32768
                        + swz((uint32_t)(wr2 * 128 + ((col & 63) >> 3) * 16)) + (col & 7) * 2;
                *reinterpret_cast<__half*>(p) = __float2half_rn(hv);
            } else {
                float acc = 0.f;
                for (int k = 0; k < KTOT; k++)
                    acc += rd_a(g_h16, KT2, m, k) * rd_b8(g_wd8, KT2, nb, cc, k, BTILE2R, 112);
                Out[(size_t)m * HIDDEN + n0 + cc] = acc * S[n0 + cc];
            }
        }
    }
#endif
}

// ---------------------------------------------------------------------------
// launch
// ---------------------------------------------------------------------------
extern "C" void kernel_launch(void* const* d_in, const int* in_sizes, int n_in,
                              void* d_out, int out_size)
{
    const float* x = nullptr; const float* w_gu = nullptr; const float* s_gu = nullptr;
    const float* w_d = nullptr; const float* s_d = nullptr;
    for (int i = 0; i < n_in; i++) {
        long long sz = in_sizes[i];
        const float* p = (const float*)d_in[i];
        if      (sz == (long long)TOKENS * HIDDEN)    x    = p;
        else if (sz == (long long)2 * INTER * HIDDEN) w_gu = p;
        else if (sz == (long long)2 * INTER)          s_gu = p;
        else if (sz == (long long)HIDDEN * INTER)     w_d  = p;
        else if (sz == (long long)HIDDEN)             s_d  = p;
    }
    float* out = (float*)d_out;

    constexpr int SMEM0 = 1024 + NSTG * (A_BYTES + BB1 + BR1);  // 230,400
    constexpr int SMEM1 = 1024 + NSTG * (A_BYTES + BB2 + BR2);  // 218,112
    cudaFuncSetAttribute(mlp_gemm<0>, cudaFuncAttributeMaxDynamicSharedMemorySize, SMEM0);
    cudaFuncSetAttribute(mlp_gemm<1>, cudaFuncAttributeMaxDynamicSharedMemorySize, SMEM1);

    // prep: zero converter/flag state, w_gu stripes [0,18), x
    conv_prep<<<(PRE_CHUNKS + X_CHUNKS) / 256, 256>>>(w_gu, x);

    // GEMM1: gate_up + SiLU*Mul -> g_h16; converter warps finish w_gu + w_d
    mlp_gemm<0><<<dim3(2 * NPAIRS, 1), THREADS, SMEM0>>>(s_gu, nullptr, w_gu, w_d);

    // GEMM2: down -> out (512 kt-units/pair, deterministic partial combine)
    mlp_gemm<1><<<dim3(2 * NPAIRS, 1), THREADS, SMEM1>>>(s_d, out, nullptr, nullptr);
}

// round 17
// speedup vs baseline: 1.0685x; 1.0451x over previous
#include <cuda_runtime.h>
#include <cuda_fp16.h>
#include <cuda_fp8.h>
#include <cstdint>

// ---------------------------------------------------------------------------
// Qwen2 FP8 MLP, fp16 tcgen05 cg2 persistent + fp8 weight delivery.
//   R17 = R14 revert (the verified 959us configuration) + PRECONV 18->12.
//   R15/R16 post-mortem: K-balanced GEMM2 combine mechanisms (atomics,
//   deterministic scratch) both cost more than the ceil(128/74) imbalance
//   they remove; GEMM2 at N=224 / 2-1 tiles per pair is its practical floor.
// ---------------------------------------------------------------------------

#if defined(__CUDA_ARCH_FEAT_SM103_ALL) || defined(__CUDA_ARCH_FEAT_SM100_ALL) || defined(__CUDA_ARCH_SPECIFIC__)
#define USE_TCGEN05 1
#else
#define USE_TCGEN05 0
#endif

namespace {
constexpr int HIDDEN = 3584;
constexpr int INTER  = 18944;
constexpr int TOKENS = 4096;

constexpr int KC      = 64;
constexpr int NSTG    = 4;
constexpr int THREADS = 448;      // w0 MMA, w1 prod, w2-3 dequant, w4-11 epi, w12-13 conv
constexpr int NPAIRS  = 74;

constexpr int A_BYTES = 32768;
constexpr int ATILE   = 65536;

constexpr int KT1 = HIDDEN / KC;              // 56
constexpr int KT2 = INTER  / KC;              // 296

constexpr int NB1      = INTER / 128;         // 148
constexpr int BB1      = 16384;
constexpr int BR1      = 8192;
constexpr int BTILE1R  = 16384;
constexpr int NT1      = (TOKENS / 512) * NB1;

constexpr int N2       = 224;
constexpr int NB2      = HIDDEN / N2;         // 16
constexpr int BB2      = 14336;
constexpr int BR2      = 7168;
constexpr int BTILE2R  = 14336;
constexpr int NT2      = (TOKENS / 512) * NB2;   // 128

constexpr int PRECONV   = 12;                         // stripes converted in prep
constexpr int PRE_CHUNKS = PRECONV * KT1 * 1024;      // 688,128
constexpr int X_CHUNKS   = (TOKENS / 512) * KT1 * 4096;
constexpr int WGU_UNITS  = (NB1 - PRECONV) * KT1;     // 7616
constexpr int WD_UNITS   = NB2 * KT2;                 // 4736
constexpr int TOTAL_UNITS = WGU_UNITS + WD_UNITS;
}

__device__ __half   g_x16[(size_t)(TOKENS / 512) * KT1 * (ATILE / 2)];
__device__ uint8_t  g_wgu8[(size_t)NB1 * KT1 * BTILE1R];
__device__ uint8_t  g_wd8 [(size_t)NB2 * KT2 * BTILE2R];
__device__ __half   g_h16[(size_t)(TOKENS / 512) * KT2 * (ATILE / 2)];

__device__ uint32_t g_uctr;            // dynamic converter work counter
__device__ uint32_t g_wdone[NB1];      // per-stripe completed (nb,kt) unit count

__host__ __device__ __forceinline__ uint32_t swz(uint32_t off) {
    return off ^ ((off >> 3) & 0x70);
}

__device__ __forceinline__ uint32_t pack_e4m3_4(float f0, float f1, float f2, float f3) {
    uint32_t w;
    asm("{\n\t.reg .b16 p0, p1;\n\t"
        "cvt.rn.satfinite.e4m3x2.f32 p0, %2, %1;\n\t"
        "cvt.rn.satfinite.e4m3x2.f32 p1, %4, %3;\n\t"
        "mov.b32 %0, {p0, p1};\n\t}"
        : "=r"(w) : "f"(f0), "f"(f1), "f"(f2), "f"(f3));
    return w;
}
__device__ __forceinline__ void fp8x4_to_h2x2(uint32_t w, uint32_t& o0, uint32_t& o1) {
    asm("{\n\t.reg .b16 lo, hi;\n\t"
        "mov.b32 {lo, hi}, %2;\n\t"
        "cvt.rn.f16x2.e4m3x2 %0, lo;\n\t"
        "cvt.rn.f16x2.e4m3x2 %1, hi;\n\t}"
        : "=r"(o0), "=r"(o1) : "r"(w));
}
__device__ __forceinline__ void stg_cg_v4(void* p, uint4 v) {
    asm volatile("st.global.cg.v4.u32 [%0], {%1,%2,%3,%4};"
                 :: "l"(p), "r"(v.x), "r"(v.y), "r"(v.z), "r"(v.w) : "memory");
}

// convert one 16-elem chunk of a w_gu tile (tile = nb*KT1+kt, chunk c 0..1023)
__device__ __forceinline__ void conv_wgu8_chunk(const float* __restrict__ src,
                                                int tile, int c) {
    const int tr = c >> 2;
    const int ch = c & 3;
    const int kt = tile % KT1;
    const int nb = tile / KT1;
    const int grow = (tr < 128) ? (nb * 128 + tr) : (INTER + nb * 128 + (tr - 128));
    const float* s = src + (size_t)grow * HIDDEN + kt * KC + ch * 16;
    uint32_t w[4];
    #pragma unroll
    for (int q = 0; q < 4; q++) {
        float4 f = reinterpret_cast<const float4*>(s)[q];
        w[q] = pack_e4m3_4(f.x, f.y, f.z, f.w);
    }
    uint8_t* dst = g_wgu8 + (size_t)tile * BTILE1R
                 + (tr >> 7) * BR1 + (tr & 127) * 64 + ch * 16;
    stg_cg_v4(dst, make_uint4(w[0], w[1], w[2], w[3]));
}

// wd8 conversion for one 16-elem chunk index (gid over NB2*KT2*896)
__device__ __forceinline__ void conv_wd8_chunk(const float* __restrict__ src, int gid) {
    const int tile = gid / 896;
    const int c    = gid % 896;
    const int tr   = c >> 2;
    const int ch   = c & 3;
    const int kt   = tile % KT2;
    const int bb   = tile / KT2;
    const int grow = bb * N2 + tr;
    const float* s = src + (size_t)grow * INTER + kt * KC + ch * 16;
    uint32_t w[4];
    #pragma unroll
    for (int q = 0; q < 4; q++) {
        float4 f = reinterpret_cast<const float4*>(s)[q];
        w[q] = pack_e4m3_4(f.x, f.y, f.z, f.w);
    }
    const int half = tr / 112;
    const int wr   = tr - half * 112;
    uint8_t* dst = g_wd8 + (size_t)tile * BTILE2R + half * BR2 + wr * 64 + ch * 16;
    *reinterpret_cast<uint4*>(dst) = make_uint4(w[0], w[1], w[2], w[3]);
}

// ---------------------------------------------------------------------------
// prep: zero converter state, convert w_gu stripes [0, PRECONV), convert x
// ---------------------------------------------------------------------------
__global__ void __launch_bounds__(256) conv_prep(const float* __restrict__ w_gu,
                                                 const float* __restrict__ x) {
    int gid = blockIdx.x * 256 + threadIdx.x;
    if (gid == 0) g_uctr = 0;
    if (gid >= 1 && gid <= NB1) g_wdone[gid - 1] = 0;

    if (gid < PRE_CHUNKS) {
        conv_wgu8_chunk(w_gu, gid >> 10, gid & 1023);
    } else {
        gid -= PRE_CHUNKS;
        if (gid < X_CHUNKS) {
            const int tile = gid >> 12;
            const int c    = gid & 4095;
            const int sr   = c >> 3;
            const int ch   = c & 7;
            const int kt   = tile % KT1;
            const int mb   = tile / KT1;
            const int rank = sr >> 8;
            const int wr   = sr & 255;
            const int m    = mb * 512 + (wr >> 7) * 256 + rank * 128 + (wr & 127);
            const float* s = x + (size_t)m * HIDDEN + kt * KC + ch * 8;
            float4 a = *reinterpret_cast<const float4*>(s);
            float4 b = *reinterpret_cast<const float4*>(s + 4);
            __half2 p0 = __floats2half2_rn(a.x, a.y);
            __half2 p1 = __floats2half2_rn(a.z, a.w);
            __half2 p2 = __floats2half2_rn(b.x, b.y);
            __half2 p3 = __floats2half2_rn(b.z, b.w);
            uint4 v = make_uint4(*reinterpret_cast<uint32_t*>(&p0),
                                 *reinterpret_cast<uint32_t*>(&p1),
                                 *reinterpret_cast<uint32_t*>(&p2),
                                 *reinterpret_cast<uint32_t*>(&p3));
            char* dst = reinterpret_cast<char*>(g_x16) + (size_t)tile * ATILE
                      + rank * 32768 + swz((uint32_t)(wr * 128 + ch * 16));
            *reinterpret_cast<uint4*>(dst) = v;
        }
    }
}

// ---------------------------------------------------------------------------
// device helpers
// ---------------------------------------------------------------------------
#if USE_TCGEN05
__device__ __forceinline__ bool elect_one() {
    uint32_t p;
    asm volatile("{\n\t.reg .pred p;\n\telect.sync _|p, 0xFFFFFFFF;\n\t"
                 "selp.b32 %0, 1, 0, p;\n\t}" : "=r"(p));
    return p != 0;
}
__device__ __forceinline__ uint32_t ctarank() {
    uint32_t r;
    asm("mov.u32 %0, %%cluster_ctarank;" : "=r"(r));
    return r;
}
__device__ __forceinline__ void mbar_init(uint32_t addr, uint32_t count) {
    asm volatile("mbarrier.init.shared.b64 [%0], %1;" :: "r"(addr), "r"(count) : "memory");
}
__device__ __forceinline__ void mbar_wait(uint32_t addr, uint32_t parity) {
    asm volatile(
        "{\n\t.reg .pred P;\n\t"
        "WL_%=:\n\t"
        "mbarrier.try_wait.parity.acquire.cta.shared::cta.b64 P, [%0], %1, 0x989680;\n\t"
        "@P bra.uni WD_%=;\n\t"
        "bra.uni WL_%=;\n\t"
        "WD_%=:\n\t}"
        :: "r"(addr), "r"(parity) : "memory");
}
__device__ __forceinline__ void mbar_expect_tx(uint32_t addr, uint32_t bytes) {
    asm volatile("mbarrier.arrive.expect_tx.shared.b64 _, [%0], %1;"
                 :: "r"(addr), "r"(bytes) : "memory");
}
__device__ __forceinline__ void mbar_arrive(uint32_t addr) {
    asm volatile("mbarrier.arrive.shared.b64 _, [%0];" :: "r"(addr) : "memory");
}
__device__ __forceinline__ void mbar_arrive_remote(uint32_t local_addr, uint32_t target_rank) {
    asm volatile(
        "{\n\t.reg .b32 ra;\n\t"
        "mapa.shared::cluster.u32 ra, %0, %1;\n\t"
        "mbarrier.arrive.shared::cluster.b64 _, [ra];\n\t}"
        :: "r"(local_addr), "r"(target_rank) : "memory");
}
__device__ __forceinline__ void bulk_g2s(uint32_t dst, const void* src, uint32_t bytes,
                                         uint32_t mbar) {
    asm volatile(
        "cp.async.bulk.shared::cluster.global.mbarrier::complete_tx::bytes "
        "[%0], [%1], %2, [%3];"
        :: "r"(dst), "l"(src), "r"(bytes), "r"(mbar) : "memory");
}
__device__ __forceinline__ void tc_alloc_cg2(uint32_t dst_smem, uint32_t ncols) {
    asm volatile("tcgen05.alloc.cta_group::2.sync.aligned.shared::cta.b32 [%0], %1;"
                 :: "r"(dst_smem), "r"(ncols) : "memory");
}
__device__ __forceinline__ void tc_relinquish_cg2() {
    asm volatile("tcgen05.relinquish_alloc_permit.cta_group::2.sync.aligned;");
}
__device__ __forceinline__ void tc_dealloc_cg2(uint32_t tmem, uint32_t ncols) {
    asm volatile("tcgen05.dealloc.cta_group::2.sync.aligned.b32 %0, %1;"
                 :: "r"(tmem), "r"(ncols));
}
__device__ __forceinline__ void tc_commit_mc_cg2(uint32_t mbar, uint16_t mask) {
    asm volatile(
        "tcgen05.commit.cta_group::2.mbarrier::arrive::one.shared::cluster.multicast::cluster.b64 "
        "[%0], %1;"
        :: "r"(mbar), "h"(mask) : "memory");
}
__device__ __forceinline__ void tc_wait_ld() {
    asm volatile("tcgen05.wait::ld.sync.aligned;" ::: "memory");
}
__device__ __forceinline__ uint64_t sdesc(uint32_t addr) {
    return ((uint64_t)((addr >> 4) & 0x3FFF))
         | (1ULL  << 16) | (64ULL << 32) | (1ULL << 46) | (2ULL << 61);
}
__device__ __forceinline__ void mma_f16_ss_cg2(uint32_t d_tmem, uint64_t ad, uint64_t bd,
                                               uint32_t idesc, uint32_t enable_d) {
    asm volatile(
        "{\n\t.reg .pred p;\n\t"
        "setp.ne.u32 p, %4, 0;\n\t"
        "tcgen05.mma.cta_group::2.kind::f16 [%0], %1, %2, %3, "
        "{%5,%5,%5,%5,%5,%5,%5,%5}, p;\n\t}"
        :: "r"(d_tmem), "l"(ad), "l"(bd), "r"(idesc), "r"(enable_d), "r"(0u)
        : "memory");
}
__device__ __forceinline__ void ldtm32(uint32_t* r, uint32_t ta) {
    asm volatile(
        "tcgen05.ld.sync.aligned.32x32b.x32.b32 "
        "{%0,%1,%2,%3,%4,%5,%6,%7,%8,%9,%10,%11,%12,%13,%14,%15,"
        "%16,%17,%18,%19,%20,%21,%22,%23,%24,%25,%26,%27,%28,%29,%30,%31}, [%32];"
        : "=r"(r[0]),  "=r"(r[1]),  "=r"(r[2]),  "=r"(r[3]),
          "=r"(r[4]),  "=r"(r[5]),  "=r"(r[6]),  "=r"(r[7]),
          "=r"(r[8]),  "=r"(r[9]),  "=r"(r[10]), "=r"(r[11]),
          "=r"(r[12]), "=r"(r[13]), "=r"(r[14]), "=r"(r[15]),
          "=r"(r[16]), "=r"(r[17]), "=r"(r[18]), "=r"(r[19]),
          "=r"(r[20]), "=r"(r[21]), "=r"(r[22]), "=r"(r[23]),
          "=r"(r[24]), "=r"(r[25]), "=r"(r[26]), "=r"(r[27]),
          "=r"(r[28]), "=r"(r[29]), "=r"(r[30]), "=r"(r[31])
        : "r"(ta));
}
#endif

// fallback read helpers
__device__ __forceinline__ float rd_a(const __half* buf, int KT, int m, int k) {
    const int mb = m >> 9, mm = m & 511;
    const int rank = (mm >> 7) & 1;
    const int wr = ((mm >> 8) << 7) | (mm & 127);
    const char* p = reinterpret_cast<const char*>(buf)
                  + ((size_t)mb * KT + (k >> 6)) * ATILE + rank * 32768
                  + swz((uint32_t)(wr * 128 + ((k & 63) >> 3) * 16)) + (k & 7) * 2;
    return __half2float(*reinterpret_cast<const __half*>(p));
}
__device__ __forceinline__ float rd_b8(const uint8_t* buf, int KT, int tile_b, int tr, int k,
                                       int tile_bytes, int half_rows) {
    const int half = tr / half_rows;
    const int wr   = tr - half * half_rows;
    const uint8_t* p = buf + ((size_t)tile_b * KT + (k >> 6)) * tile_bytes
                     + half * (tile_bytes / 2) + wr * 64 + (k & 63);
    __nv_fp8_e4m3 v;
    *reinterpret_cast<uint8_t*>(&v) = *p;
    return float(v);
}

// ---------------------------------------------------------------------------
// Persistent GEMM. grid (148,1,1), cluster (2,1,1), 448 threads.
// MODE 0: mb-major tiles; warps 12-13 = chip-wide dynamic w_gu/w_d converter.
// MODE 1: 2/1 tiles per pair (R14 schedule).
// ---------------------------------------------------------------------------
template <int MODE>
__global__ void __launch_bounds__(THREADS, 1) __cluster_dims__(2, 1, 1)
mlp_gemm(const float* __restrict__ S, float* __restrict__ Out,
         const float* __restrict__ Wgu32, const float* __restrict__ Wd32)
{
    constexpr int KT      = (MODE == 0) ? KT1 : KT2;
    constexpr int NMMA    = (MODE == 0) ? 256 : N2;
    constexpr int BBYTES  = (MODE == 0) ? BB1 : BB2;
    constexpr int BRAW    = (MODE == 0) ? BR1 : BR2;
    constexpr int BTILER  = (MODE == 0) ? BTILE1R : BTILE2R;
    constexpr int STG_B   = A_BYTES + BBYTES + BRAW;
    constexpr int CCH     = (MODE == 0) ? 4 : 7;
    constexpr int DQU     = (MODE == 0) ? 8 : 7;
    const int pair = blockIdx.x >> 1;
    const int ntp  = (MODE == 0) ? (NT1 / NPAIRS)
                                 : ((pair < NT2 - NPAIRS) ? 2 : 1);

    extern __shared__ char smem[];
    const int t    = threadIdx.x;
    const int wid  = t >> 5;
    const int lane = t & 31;

#if USE_TCGEN05
    constexpr uint32_t IDESC = (1u << 4) | ((uint32_t)(NMMA / 8) << 17) | (16u << 24);

    const uint32_t sbase     = (uint32_t)__cvta_generic_to_shared(smem);
    const uint32_t tptr_addr = sbase;
    const uint32_t bar_full  = sbase + 8;
    const uint32_t bar_empty = bar_full + NSTG * 8;
    const uint32_t bar_deq   = bar_empty + NSTG * 8;
    const uint32_t bar_done  = bar_deq + NSTG * 8;
    const uint32_t bar_elo   = bar_done + 8;
    const uint32_t bar_ehi   = bar_done + 16;
    const uint32_t data_u    = (sbase + 256 + 1023) & ~1023u;
    const uint32_t rank      = ctarank();

    // mb-major for BOTH modes: stripes demanded progressively
    auto tile_mb_nb = [&](int tl, int& mb, int& nb) {
        const int idx = tl * NPAIRS + pair;
        mb = idx & 7; nb = idx >> 3;
    };

    if (wid == 0) { tc_alloc_cg2(tptr_addr, 512); tc_relinquish_cg2(); }
    if (t == 0) {
        for (int s = 0; s < NSTG; s++) {
            mbar_init(bar_full  + s * 8, 1);
            mbar_init(bar_empty + s * 8, 1);
            mbar_init(bar_deq   + s * 8, 4);
        }
        mbar_init(bar_done, 1);
        mbar_init(bar_elo, 8);
        mbar_init(bar_ehi, 8);
    }
    __syncthreads();
    asm volatile("barrier.cluster.arrive.aligned;" ::: "memory");
    asm volatile("barrier.cluster.wait.aligned;"   ::: "memory");

    uint32_t tmem;
    asm volatile("ld.shared.b32 %0, [%1];" : "=r"(tmem) : "r"(tptr_addr));

    const char*    Abuf = reinterpret_cast<const char*>((MODE == 0) ? g_x16 : g_h16);
    const uint8_t* Bbuf = (MODE == 0) ? g_wgu8 : g_wd8;

    if (t == 32) {
        // ---------------- TMA producer ----------------
        uint32_t g = 0;
        for (int tl = 0; tl < ntp; tl++) {
            int mb, nb; tile_mb_nb(tl, mb, nb);
            if (MODE == 0 && nb >= PRECONV) {
                // wait for stripe nb fully converted (56 units)
                uint32_t v;
                const uint32_t* fp = &g_wdone[nb];
                do {
                    asm volatile("ld.acquire.gpu.global.u32 %0, [%1];"
                                 : "=r"(v) : "l"(fp) : "memory");
                } while (v < (uint32_t)KT1);
            }
            const char*    a_base = Abuf + (size_t)mb * KT * ATILE + rank * 32768;
            const uint8_t* b_base = Bbuf + (size_t)nb * KT * BTILER + rank * BRAW;
            for (int kt = 0; kt < KT; kt++, g++) {
                const uint32_t s = g & (NSTG - 1);
                if (g >= NSTG) mbar_wait(bar_empty + s * 8, ((g >> 2) - 1) & 1);
                const uint32_t As = data_u + s * STG_B;
                mbar_expect_tx(bar_full + s * 8, A_BYTES + BRAW);
                bulk_g2s(As, a_base + (size_t)kt * ATILE, A_BYTES, bar_full + s * 8);
                bulk_g2s(As + A_BYTES + BBYTES, b_base + (size_t)kt * BTILER, BRAW,
                         bar_full + s * 8);
            }
        }
    } else if (wid == 2 || wid == 3) {
        // ---------------- dequant warps: fp8 raw -> fp16 SW128 in SMEM ----------
        const int wt = t - 64;
        const uint32_t total = (uint32_t)ntp * KT;
        for (uint32_t g = 0; g < total; g++) {
            const uint32_t s = g & (NSTG - 1);
            mbar_wait(bar_full + s * 8, (g >> 2) & 1);
            const uint32_t As  = data_u + s * STG_B;
            const uint32_t dst = As + A_BYTES;
            const uint32_t raw = dst + BBYTES;
            #pragma unroll
            for (int j = 0; j < DQU; j++) {
                const int u   = wt + 64 * j;
                const int row = u >> 2;
                const int ch  = u & 3;
                uint4 r;
                asm volatile("ld.shared.v4.u32 {%0,%1,%2,%3}, [%4];"
                             : "=r"(r.x), "=r"(r.y), "=r"(r.z), "=r"(r.w)
                             : "r"(raw + row * 64 + ch * 16));
                uint32_t o0, o1, o2, o3, o4, o5, o6, o7;
                fp8x4_to_h2x2(r.x, o0, o1);
                fp8x4_to_h2x2(r.y, o2, o3);
                fp8x4_to_h2x2(r.z, o4, o5);
                fp8x4_to_h2x2(r.w, o6, o7);
                const uint32_t ob = (uint32_t)(row * 128 + ch * 32);
                asm volatile("st.shared.v4.b32 [%0], {%1,%2,%3,%4};"
                             :: "r"(dst + swz(ob)), "r"(o0), "r"(o1), "r"(o2), "r"(o3)
                             : "memory");
                asm volatile("st.shared.v4.b32 [%0], {%1,%2,%3,%4};"
                             :: "r"(dst + swz(ob + 16)), "r"(o4), "r"(o5), "r"(o6), "r"(o7)
                             : "memory");
            }
            asm volatile("fence.proxy.async.shared::cta;" ::: "memory");
            if (elect_one()) {
                if (rank == 0) mbar_arrive(bar_deq + s * 8);
                else           mbar_arrive_remote(bar_deq + s * 8, 0);
            }
        }
    } else if (wid == 0 && rank == 0) {
        // ---------------- MMA issuer (leader) ----------------
        if (elect_one()) {
            uint32_t g = 0;
            for (int tl = 0; tl < ntp; tl++) {
                for (int kt = 0; kt < KT; kt++, g++) {
                    const uint32_t s = g & (NSTG - 1);
                    mbar_wait(bar_deq + s * 8, (g >> 2) & 1);
                    const uint32_t As = data_u + s * STG_B;
                    const uint64_t ad0 = sdesc(As);
                    const uint64_t ad1 = sdesc(As + 16384);
                    const uint64_t bd  = sdesc(As + A_BYTES);
                    if (kt == 0) {
                        if (tl > 0) mbar_wait(bar_elo, (tl - 1) & 1);
                        #pragma unroll
                        for (int kk = 0; kk < 4; kk++)
                            mma_f16_ss_cg2(tmem, ad0 + 2 * kk, bd + 2 * kk, IDESC, kk > 0);
                        if (tl > 0) mbar_wait(bar_ehi, (tl - 1) & 1);
                        #pragma unroll
                        for (int kk = 0; kk < 4; kk++)
                            mma_f16_ss_cg2(tmem + NMMA, ad1 + 2 * kk, bd + 2 * kk, IDESC, kk > 0);
                    } else {
                        #pragma unroll
                        for (int kk = 0; kk < 4; kk++) {
                            mma_f16_ss_cg2(tmem,        ad0 + 2 * kk, bd + 2 * kk, IDESC, 1);
                            mma_f16_ss_cg2(tmem + NMMA, ad1 + 2 * kk, bd + 2 * kk, IDESC, 1);
                        }
                    }
                    tc_commit_mc_cg2(bar_empty + s * 8, (uint16_t)0x3);
                }
                tc_commit_mc_cg2(bar_done, (uint16_t)0x3);
            }
        }
    } else if (wid >= 4 && wid < 12) {
        // ---------------- epilogue warps ----------------
        const int mh = (wid >> 2) - 1;
        const int sp = wid & 3;
        const uint32_t tbase = tmem + mh * NMMA;
        const uint32_t ebar  = (mh == 0) ? bar_elo : bar_ehi;
        for (int tl = 0; tl < ntp; tl++) {
            int mb, nb; tile_mb_nb(tl, mb, nb);
            mbar_wait(bar_done, tl & 1);
            asm volatile("tcgen05.fence::after_thread_sync;" ::: "memory");
            const int m = mb * 512 + mh * 256 + (int)rank * 128 + sp * 32 + lane;

            if (MODE == 0) {
                const int n0 = nb * 128;
                const int mm = m & 511;
                const int rank2 = (mm >> 7) & 1;
                const int wr2 = ((mm >> 8) << 7) | (mm & 127);
                char* hb = reinterpret_cast<char*>(g_h16)
                         + (size_t)(m >> 9) * KT2 * ATILE + rank2 * 32768;
                #pragma unroll
                for (int c = 0; c < 4; c++) {
                    const int cb = c * 32;
                    uint32_t gr[32], ur[32];
                    ldtm32(gr, tbase + cb);
                    ldtm32(ur, tbase + 128 + cb);
                    tc_wait_ld();
                    if (c == 3) {
                        if (elect_one()) mbar_arrive_remote(ebar, 0);
                    }
                    uint32_t oh[16];
                    #pragma unroll
                    for (int p = 0; p < 16; p++) {
                        const int i = 2 * p;
                        const int n = n0 + cb + i;
                        float g0 = __uint_as_float(gr[i])     * __ldg(S + n);
                        float g1 = __uint_as_float(gr[i + 1]) * __ldg(S + n + 1);
                        float u0 = __uint_as_float(ur[i])     * __ldg(S + INTER + n);
                        float u1 = __uint_as_float(ur[i + 1]) * __ldg(S + INTER + n + 1);
                        float h0 = __fdividef(g0, 1.0f + __expf(-g0)) * u0;
                        float h1 = __fdividef(g1, 1.0f + __expf(-g1)) * u1;
                        __half2 ph = __floats2half2_rn(h0, h1);
                        oh[p] = *reinterpret_cast<uint32_t*>(&ph);
                    }
                    #pragma unroll
                    for (int q = 0; q < 4; q++) {
                        const int col = n0 + cb + q * 8;
                        char* tb = hb + (size_t)(col >> 6) * ATILE;
                        const uint32_t off = swz((uint32_t)(wr2 * 128 + ((col & 63) >> 3) * 16));
                        *reinterpret_cast<uint4*>(tb + off) =
                            make_uint4(oh[4 * q], oh[4 * q + 1], oh[4 * q + 2], oh[4 * q + 3]);
                    }
                }
            } else {
                const int n0 = nb * N2;
                float* op = Out + (size_t)m * HIDDEN + n0;
                #pragma unroll
                for (int c = 0; c < CCH; c++) {
                    const int cb = c * 32;
                    uint32_t dr[32];
                    ldtm32(dr, tbase + cb);
                    tc_wait_ld();
                    if (c == CCH - 1) {
                        if (elect_one()) mbar_arrive_remote(ebar, 0);
                    }
                    #pragma unroll
                    for (int q = 0; q < 8; q++) {
                        float r[4];
                        #pragma unroll
                        for (int j = 0; j < 4; j++) {
                            const int i = q * 4 + j;
                            r[j] = __uint_as_float(dr[i]) * __ldg(S + n0 + cb + i);
                        }
                        reinterpret_cast<float4*>(op + cb)[q] =
                            make_float4(r[0], r[1], r[2], r[3]);
                    }
                }
            }
        }
    } else if (MODE == 0 && wid >= 12) {
        // ---------------- chip-wide dynamic converter (per-warp units) --------
        for (;;) {
            uint32_t u;
            if (lane == 0) u = atomicAdd(&g_uctr, 1u);
            u = __shfl_sync(0xFFFFFFFFu, u, 0);
            if (u >= (uint32_t)TOTAL_UNITS) break;
            if (u < (uint32_t)WGU_UNITS) {
                const int tile = PRECONV * KT1 + (int)u;   // ascending nb
                const int nb   = tile / KT1;
                #pragma unroll 4
                for (int j = 0; j < 32; j++)
                    conv_wgu8_chunk(Wgu32, tile, lane + 32 * j);
                __syncwarp();
                if (lane == 0) {
                    uint32_t* dp = &g_wdone[nb];
                    asm volatile("red.release.gpu.global.add.u32 [%0], %1;"
                                 :: "l"(dp), "r"(1u) : "memory");
                }
            } else {
                const int t2 = (int)u - WGU_UNITS;
                #pragma unroll 4
                for (int j = 0; j < 28; j++)
                    conv_wd8_chunk(Wd32, t2 * 896 + lane + 32 * j);
            }
        }
    }

    __syncthreads();
    if (wid == 0) tc_dealloc_cg2(tmem, 512);
    asm volatile("barrier.cluster.arrive.aligned;" ::: "memory");
    asm volatile("barrier.cluster.wait.aligned;"   ::: "memory");

#else
    // non-103a compile pass only (never selected at runtime on GB300)
    (void)smem; (void)lane;
    const int rankf = blockIdx.x & 1;
    constexpr int KTOT = (MODE == 0) ? HIDDEN : INTER;
    constexpr int NCOL = (MODE == 0) ? 128 : N2;
    if (MODE == 0) {
        // convert every stripe this CTA's tiles need (duplicates benign)
        for (int tl = 0; tl < ntp; tl++) {
            const int idx = tl * NPAIRS + pair;
            const int nb = idx >> 3;
            for (int u = t; u < KT1 * 1024; u += THREADS)
                conv_wgu8_chunk(Wgu32, nb * KT1 + (u >> 10), u & 1023);
        }
        for (int g = (int)blockIdx.x * THREADS + t; g < NB2 * KT2 * 896;
             g += 148 * THREADS)
            conv_wd8_chunk(Wd32, g);
        __syncthreads();
    }
    for (int tl = 0; tl < ntp; tl++) {
        const int idx = tl * NPAIRS + pair;
        const int mb = idx & 7, nb = idx >> 3;
        const int n0 = nb * NCOL;
        for (int o = t; o < 256 * NCOL; o += THREADS) {
            const int rr = o / NCOL, cc = o % NCOL;
            const int m = mb * 512 + (rr >> 7) * 256 + rankf * 128 + (rr & 127);
            if (MODE == 0) {
                float accg = 0.f, accu = 0.f;
                for (int k = 0; k < KTOT; k++) {
                    float a = rd_a(g_x16, KT1, m, k);
                    accg += a * rd_b8(g_wgu8, KT1, nb, cc, k, BTILE1R, 128);
                    accu += a * rd_b8(g_wgu8, KT1, nb, 128 + cc, k, BTILE1R, 128);
                }
                float g = accg * S[n0 + cc], u = accu * S[INTER + n0 + cc];
                float hv = g / (1.0f + __expf(-g)) * u;
                const int col = n0 + cc;
                const int mm = m & 511;
                const int rank2 = (mm >> 7) & 1;
                const int wr2 = ((mm >> 8) << 7) | (mm & 127);
                char* p = reinterpret_cast<char*>(g_h16)
                        + ((size_t)(m >> 9) * KT2 + (col >> 6)) * ATILE + rank2 * 32768
                        + swz((uint32_t)(wr2 * 128 + ((col & 63) >> 3) * 16)) + (col & 7) * 2;
                *reinterpret_cast<__half*>(p) = __float2half_rn(hv);
            } else {
                float acc = 0.f;
                for (int k = 0; k < KTOT; k++)
                    acc += rd_a(g_h16, KT2, m, k) * rd_b8(g_wd8, KT2, nb, cc, k, BTILE2R, 112);
                Out[(size_t)m * HIDDEN + n0 + cc] = acc * S[n0 + cc];
            }
        }
    }
#endif
}

// ---------------------------------------------------------------------------
// launch
// ---------------------------------------------------------------------------
extern "C" void kernel_launch(void* const* d_in, const int* in_sizes, int n_in,
                              void* d_out, int out_size)
{
    const float* x = nullptr; const float* w_gu = nullptr; const float* s_gu = nullptr;
    const float* w_d = nullptr; const float* s_d = nullptr;
    for (int i = 0; i < n_in; i++) {
        long long sz = in_sizes[i];
        const float* p = (const float*)d_in[i];
        if      (sz == (long long)TOKENS * HIDDEN)    x    = p;
        else if (sz == (long long)2 * INTER * HIDDEN) w_gu = p;
        else if (sz == (long long)2 * INTER)          s_gu = p;
        else if (sz == (long long)HIDDEN * INTER)     w_d  = p;
        else if (sz == (long long)HIDDEN)             s_d  = p;
    }
    float* out = (float*)d_out;

    constexpr int SMEM0 = 1024 + NSTG * (A_BYTES + BB1 + BR1);  // 230,400
    constexpr int SMEM1 = 1024 + NSTG * (A_BYTES + BB2 + BR2);  // 218,112
    cudaFuncSetAttribute(mlp_gemm<0>, cudaFuncAttributeMaxDynamicSharedMemorySize, SMEM0);
    cudaFuncSetAttribute(mlp_gemm<1>, cudaFuncAttributeMaxDynamicSharedMemorySize, SMEM1);

    // prep: zero converter state, w_gu stripes [0,12), x
    conv_prep<<<(PRE_CHUNKS + X_CHUNKS) / 256, 256>>>(w_gu, x);

    // GEMM1: gate_up + SiLU*Mul -> g_h16; remaining w_gu + all w_d converted
    // by in-kernel dynamic converter warps
    mlp_gemm<0><<<dim3(2 * NPAIRS, 1), THREADS, SMEM0>>>(s_gu, nullptr, w_gu, w_d);

    // GEMM2: down -> out
    mlp_gemm<1><<<dim3(2 * NPAIRS, 1), THREADS, SMEM1>>>(s_d, out, nullptr, nullptr);
}